// round 11
// baseline (speedup 1.0000x reference)
#include <cuda_runtime.h>
#include <cuda_bf16.h>
#include <mma.h>
#include <cuda_pipeline.h>

using namespace nvcuda;

#define BATCH 128
#define SEQ   256
#define NIN   512
#define NH    1024
#define NOUT  512

typedef __nv_bfloat16 bf16;

// proj GEMM tiling (unchanged, working)
#define BM 64
#define BN 64
#define BK 32
#define SKS 48
#define PSTAGES 3
#define PSTB (4 * BM * SKS)

// rec-step: block = 64 m x (16 n per gate x 4 gates), K-chunk 64, bulk-copy fed
#define RN 16
#define RKC 64
#define RNCH (NH / RKC)        /* 16 */
#define RSTG 3
#define SRS 72                 /* stage row stride in bf16 (144 B) */
#define SROWS 256              /* 128 A rows (hi+lo) + 128 B rows (hi+lo) */
#define STG_BYTES (SROWS * SRS * 2)    /* 36864 */
#define TILE_BASE 1024
#define REC_SMEM (TILE_BASE + RSTG * STG_BYTES)   /* 111616 */
#define TX_BYTES 32768         /* 256 copies x 128 B */

// fp32 out_gemm tiling
#define TM 64
#define TN 64
#define TK 16
#define SROW 68

// ---------------- scratch (device globals) ----------------
__device__ float g_xproj[(size_t)4 * SEQ * BATCH * NH];
__device__ float g_h[BATCH * NH];
__device__ float g_c[BATCH * NH];
__device__ bf16  g_hA_hi[BATCH * NH];
__device__ bf16  g_hA_lo[BATCH * NH];
__device__ bf16  g_hB_hi[BATCH * NH];
__device__ bf16  g_hB_lo[BATCH * NH];
__device__ bf16  g_Wh_hi[(size_t)4 * NH * NH];
__device__ bf16  g_Wh_lo[(size_t)4 * NH * NH];
__device__ bf16  g_Wx_hi[(size_t)4 * NH * NIN];
__device__ bf16  g_Wx_lo[(size_t)4 * NH * NIN];
__device__ bf16  g_x_hi[(size_t)BATCH * SEQ * NIN];
__device__ bf16  g_x_lo[(size_t)BATCH * SEQ * NIN];

struct Ptr4 { const float* p[4]; };

__device__ __forceinline__ float fast_sigmoid(float x) { return 1.f / (1.f + __expf(-x)); }
__device__ __forceinline__ float fast_tanh(float x)    { return 2.f * fast_sigmoid(2.f * x) - 1.f; }

// ---------------- mbarrier / bulk-copy helpers (base sm_90 features only) ----
__device__ __forceinline__ void mbar_init(uint32_t a, uint32_t cnt)
{
    asm volatile("mbarrier.init.shared.b64 [ %0 ], %1;" :: "r"(a), "r"(cnt) : "memory");
}
__device__ __forceinline__ void mbar_expect_tx(uint32_t a, uint32_t bytes)
{
    asm volatile("mbarrier.arrive.expect_tx.shared.b64 _, [ %0 ], %1;"
                 :: "r"(a), "r"(bytes) : "memory");
}
__device__ __forceinline__ void mbar_wait(uint32_t a, uint32_t parity)
{
    asm volatile(
        "{ .reg .pred P1; "
        "LAB_%=: mbarrier.try_wait.parity.acquire.cta.shared::cta.b64 P1, [ %0 ], %1; "
        "@P1 bra DONE_%=; "
        "bra LAB_%=; "
        "DONE_%=: }"
        :: "r"(a), "r"(parity) : "memory");
}
__device__ __forceinline__ void bulk_copy(uint32_t dst, const void* src, uint32_t bytes,
                                          uint32_t mbar)
{
    asm volatile(
        "cp.async.bulk.shared::cluster.global.mbarrier::complete_tx::bytes "
        "[ %0 ], [ %1 ], %2, [ %3 ];"
        :: "r"(dst), "l"(src), "r"(bytes), "r"(mbar) : "memory");
}
__device__ __forceinline__ void fence_async_shared()
{
    asm volatile("fence.proxy.async.shared::cta;" ::: "memory");
}

// ---------------- fused setup: init + all splits in ONE launch ----------------
__global__ __launch_bounds__(256) void fused_setup(const float* __restrict__ x,
                                                   Ptr4 Wh, Ptr4 Wx)
{
    const size_t idx = (size_t)blockIdx.x * 256 + threadIdx.x;
    {
        float v = x[idx];
        bf16 hv = __float2bfloat16_rn(v);
        g_x_hi[idx] = hv;
        g_x_lo[idx] = __float2bfloat16_rn(v - __bfloat162float(hv));
    }
    if (idx < (size_t)4 * NH * NH) {
        int gate = (int)(idx >> 20);
        float v = Wh.p[gate][idx & ((1u << 20) - 1)];
        bf16 hv = __float2bfloat16_rn(v);
        g_Wh_hi[idx] = hv;
        g_Wh_lo[idx] = __float2bfloat16_rn(v - __bfloat162float(hv));
    }
    if (idx < (size_t)4 * NH * NIN) {
        int gate = (int)(idx >> 19);
        float v = Wx.p[gate][idx & ((1u << 19) - 1)];
        bf16 hv = __float2bfloat16_rn(v);
        g_Wx_hi[idx] = hv;
        g_Wx_lo[idx] = __float2bfloat16_rn(v - __bfloat162float(hv));
    }
    if (idx < (size_t)BATCH * NH) {
        g_h[idx] = 0.f;
        g_c[idx] = 0.f;
        g_hA_hi[idx] = __float2bfloat16_rn(0.f);
        g_hA_lo[idx] = __float2bfloat16_rn(0.f);
    }
}

// ---------------- fused recurrent step (bulk-copy fed WMMA) ----------------
// grid (NH/RN=64, BATCH/64=2) = 128 blocks, 512 threads (16 warps).
// Stage rows (144B stride): [0,64) A hi (m), [64,128) A lo,
// [128,192) B hi (gate*16+n), [192,256) B lo. One 128B bulk copy per row.
// Warp (gp=warp>>2 gate, wq=warp&3 m-quarter) computes 16m x 16n.
__global__ __launch_bounds__(512) void rec_step(int t)
{
    extern __shared__ __align__(128) unsigned char dynsm[];
    const uint32_t smem_u32 = (uint32_t)__cvta_generic_to_shared(dynsm);

    const int par = t & 1;
    const bf16* __restrict__ hin_hi = par ? g_hB_hi : g_hA_hi;
    const bf16* __restrict__ hin_lo = par ? g_hB_lo : g_hA_lo;
    bf16* __restrict__ hout_hi = par ? g_hA_hi : g_hB_hi;
    bf16* __restrict__ hout_lo = par ? g_hA_lo : g_hB_lo;

    const int tid   = threadIdx.x;
    const int warp  = tid >> 5;
    const int nbase = blockIdx.x * RN;
    const int mbase = blockIdx.y * 64;

    if (tid == 0) {
        mbar_init(smem_u32 + 0, 1);
        mbar_init(smem_u32 + 8, 1);
        mbar_init(smem_u32 + 16, 1);
    }

    // epilogue operand prefetch (independent of GEMM)
    const int erow  = tid >> 3;        // 0..63
    const int ecol2 = (tid & 7) * 2;   // 0..14
    const int em = mbase + erow;
    const int en = nbase + ecol2;
    const size_t BH = (size_t)BATCH * NH;
    float2 xf = *(const float2*)&g_xproj[((size_t)(0 * SEQ) + t) * BH + (size_t)em * NH + en];
    float2 xi = *(const float2*)&g_xproj[((size_t)(1 * SEQ) + t) * BH + (size_t)em * NH + en];
    float2 xg = *(const float2*)&g_xproj[((size_t)(2 * SEQ) + t) * BH + (size_t)em * NH + en];
    float2 xo = *(const float2*)&g_xproj[((size_t)(3 * SEQ) + t) * BH + (size_t)em * NH + en];
    float2 cv = *(const float2*)&g_c[(size_t)em * NH + en];

    // per-thread bulk-copy source (tid < 256): one 128B row segment per chunk
    const bf16* gsrc = 0;
    uint32_t drow = 0;
    if (tid < 256) {
        const int row = tid;
        drow = (uint32_t)(row * (SRS * 2));   // byte offset within stage
        if (row < 64) {
            gsrc = hin_hi + (size_t)(mbase + row) * NH;
        } else if (row < 128) {
            gsrc = hin_lo + (size_t)(mbase + row - 64) * NH;
        } else if (row < 192) {
            int idx = row - 128;
            gsrc = g_Wh_hi + (size_t)(idx >> 4) * NH * NH + (size_t)(nbase + (idx & 15)) * NH;
        } else {
            int idx = row - 192;
            gsrc = g_Wh_lo + (size_t)(idx >> 4) * NH * NH + (size_t)(nbase + (idx & 15)) * NH;
        }
    }

    __syncthreads();   // mbarriers visible before any complete_tx

    // prologue: chunks 0,1
    #pragma unroll
    for (int s = 0; s < RSTG - 1; s++) {
        if (tid == 0) { mbar_expect_tx(smem_u32 + s * 8, TX_BYTES); }
        if (tid < 256) {
            bulk_copy(smem_u32 + TILE_BASE + s * STG_BYTES + drow,
                      gsrc + s * RKC, 128u, smem_u32 + s * 8);
        }
    }

    wmma::fragment<wmma::accumulator, 16, 16, 16, float> acc;
    wmma::fill_fragment(acc, 0.0f);

    const int gp = warp >> 2;   // gate
    const int wq = warp & 3;    // m-quarter

    for (int c = 0; c < RNCH; c++) {
        mbar_wait(smem_u32 + (c % RSTG) * 8, (uint32_t)((c / RSTG) & 1));
        __syncthreads();   // all threads done reading stage (c-1)%RSTG

        const int cn = c + RSTG - 1;
        if (cn < RNCH) {
            if (tid == 0) { mbar_expect_tx(smem_u32 + (cn % RSTG) * 8, TX_BYTES); }
            if (tid < 256) {
                fence_async_shared();
                bulk_copy(smem_u32 + TILE_BASE + (cn % RSTG) * STG_BYTES + drow,
                          gsrc + cn * RKC, 128u, smem_u32 + (cn % RSTG) * 8);
            }
        }

        bf16* sp = (bf16*)(dynsm + TILE_BASE + (c % RSTG) * STG_BYTES);
        #pragma unroll
        for (int ks = 0; ks < 4; ks++) {
            wmma::fragment<wmma::matrix_b, 16, 16, 16, bf16, wmma::col_major> fbh;
            wmma::fragment<wmma::matrix_b, 16, 16, 16, bf16, wmma::col_major> fbl;
            wmma::load_matrix_sync(fbh, sp + (128 + gp * 16) * SRS + ks * 16, SRS);
            wmma::load_matrix_sync(fbl, sp + (192 + gp * 16) * SRS + ks * 16, SRS);

            wmma::fragment<wmma::matrix_a, 16, 16, 16, bf16, wmma::row_major> fah;
            wmma::fragment<wmma::matrix_a, 16, 16, 16, bf16, wmma::row_major> fal;
            wmma::load_matrix_sync(fah, sp + (wq * 16) * SRS + ks * 16, SRS);
            wmma::load_matrix_sync(fal, sp + (64 + wq * 16) * SRS + ks * 16, SRS);

            wmma::mma_sync(acc, fah, fbh, acc);
            wmma::mma_sync(acc, fah, fbl, acc);
            wmma::mma_sync(acc, fal, fbh, acc);
        }
    }

    __syncthreads();
    // overlay fp32 stage on pipeline buffers: stage[gate][m 0..63][n 0..15]
    float* stage = (float*)(dynsm + TILE_BASE);
    wmma::store_matrix_sync(stage + (gp * 64 + wq * 16) * RN, acc, RN, wmma::mem_row_major);
    __syncthreads();

    // cell update: 64m x 16n = 1024 cells, 2 consecutive n per thread
    {
        float2 pf = *(float2*)(stage + (0 * 64 + erow) * RN + ecol2);
        float2 pi = *(float2*)(stage + (1 * 64 + erow) * RN + ecol2);
        float2 pg = *(float2*)(stage + (2 * 64 + erow) * RN + ecol2);
        float2 po = *(float2*)(stage + (3 * 64 + erow) * RN + ecol2);

        float hv[2];
        float cn2[2];
        float pfv[2]; float piv[2]; float pgv[2]; float pov[2];
        float xfv[2]; float xiv[2]; float xgv[2]; float xov[2];
        float ccv[2];
        pfv[0]=pf.x; pfv[1]=pf.y;
        piv[0]=pi.x; piv[1]=pi.y;
        pgv[0]=pg.x; pgv[1]=pg.y;
        pov[0]=po.x; pov[1]=po.y;
        xfv[0]=xf.x; xfv[1]=xf.y;
        xiv[0]=xi.x; xiv[1]=xi.y;
        xgv[0]=xg.x; xgv[1]=xg.y;
        xov[0]=xo.x; xov[1]=xo.y;
        ccv[0]=cv.x; ccv[1]=cv.y;

        #pragma unroll
        for (int j = 0; j < 2; j++) {
            float fg = fast_sigmoid(pfv[j] + xfv[j]);
            float ig = fast_sigmoid(piv[j] + xiv[j]);
            float gg = fast_tanh(pgv[j] + xgv[j]);
            float og = fast_sigmoid(pov[j] + xov[j]);
            float c2 = fg * ccv[j] + ig * gg;
            cn2[j] = c2;
            hv[j] = og * fast_tanh(c2);
        }

        *(float2*)&g_c[(size_t)em * NH + en] = make_float2(cn2[0], cn2[1]);
        *(float2*)&g_h[(size_t)em * NH + en] = make_float2(hv[0], hv[1]);

        __nv_bfloat162 hh = __floats2bfloat162_rn(hv[0], hv[1]);
        float l0 = hv[0] - __bfloat162float(__low2bfloat16(hh));
        float l1 = hv[1] - __bfloat162float(__high2bfloat16(hh));
        *(__nv_bfloat162*)(hout_hi + (size_t)em * NH + en) = hh;
        *(__nv_bfloat162*)(hout_lo + (size_t)em * NH + en) = __floats2bfloat162_rn(l0, l1);
    }
}

// ---------------- bf16x3 input-projection GEMM (cp.async 3-stage, unchanged) ----------------
__global__ __launch_bounds__(256) void proj_gemm(Ptr4 Bias)
{
    extern __shared__ __align__(16) unsigned char dynsm[];
    bf16* stg = (bf16*)dynsm;

    const int gate = blockIdx.z;
    const bf16* __restrict__ Bhi = g_Wx_hi + (size_t)gate * NH * NIN;
    const bf16* __restrict__ Blo = g_Wx_lo + (size_t)gate * NH * NIN;
    const float* __restrict__ bias = Bias.p[gate];

    const int tid   = threadIdx.x;
    const int warp  = tid >> 5;
    const int wm    = warp >> 2;
    const int wn    = warp & 3;
    const int mbase = blockIdx.y * BM;
    const int nbase = blockIdx.x * BN;

    const bf16* gsrc[4];
    int soff[4];
    #pragma unroll
    for (int l = 0; l < 4; l++) {
        int idx = l * 256 + tid;
        int p   = idx >> 8;
        int w   = idx & 255;
        int row = w >> 2;
        int q   = (w & 3) * 8;
        soff[l] = (p * BM + row) * SKS + q;
        if (p == 0) {
            gsrc[l] = g_x_hi + (size_t)(mbase + row) * NIN + q;
        } else if (p == 1) {
            gsrc[l] = g_x_lo + (size_t)(mbase + row) * NIN + q;
        } else if (p == 2) {
            gsrc[l] = Bhi + (size_t)(nbase + row) * NIN + q;
        } else {
            gsrc[l] = Blo + (size_t)(nbase + row) * NIN + q;
        }
    }

    wmma::fragment<wmma::accumulator, 16, 16, 16, float> acc0;
    wmma::fragment<wmma::accumulator, 16, 16, 16, float> acc1;
    wmma::fill_fragment(acc0, 0.0f);
    wmma::fill_fragment(acc1, 0.0f);

    const int NC = NIN / BK;   // 16

    #pragma unroll
    for (int s = 0; s < PSTAGES - 1; s++) {
        const int ko = s * BK;
        #pragma unroll
        for (int l = 0; l < 4; l++) {
            __pipeline_memcpy_async(stg + s * PSTB + soff[l], gsrc[l] + ko, 16);
        }
        __pipeline_commit();
    }

    for (int c = 0; c < NC; c++) {
        __pipeline_wait_prior(PSTAGES - 2);
        __syncthreads();

        const int cn = c + PSTAGES - 1;
        if (cn < NC) {
            const int ko = cn * BK;
            const int ds = cn % PSTAGES;
            #pragma unroll
            for (int l = 0; l < 4; l++) {
                __pipeline_memcpy_async(stg + ds * PSTB + soff[l], gsrc[l] + ko, 16);
            }
        }
        __pipeline_commit();

        bf16* sp = stg + (c % PSTAGES) * PSTB;
        #pragma unroll
        for (int ks = 0; ks < 2; ks++) {
            wmma::fragment<wmma::matrix_b, 16, 16, 16, bf16, wmma::col_major> fbh;
            wmma::fragment<wmma::matrix_b, 16, 16, 16, bf16, wmma::col_major> fbl;
            wmma::load_matrix_sync(fbh, sp + (2 * BM + wn * 16) * SKS + ks * 16, SKS);
            wmma::load_matrix_sync(fbl, sp + (3 * BM + wn * 16) * SKS + ks * 16, SKS);

            wmma::fragment<wmma::matrix_a, 16, 16, 16, bf16, wmma::row_major> fah;
            wmma::fragment<wmma::matrix_a, 16, 16, 16, bf16, wmma::row_major> fal;
            wmma::load_matrix_sync(fah, sp + (0 * BM + wm * 32) * SKS + ks * 16, SKS);
            wmma::load_matrix_sync(fal, sp + (1 * BM + wm * 32) * SKS + ks * 16, SKS);
            wmma::mma_sync(acc0, fah, fbh, acc0);
            wmma::mma_sync(acc0, fah, fbl, acc0);
            wmma::mma_sync(acc0, fal, fbh, acc0);

            wmma::load_matrix_sync(fah, sp + (0 * BM + wm * 32 + 16) * SKS + ks * 16, SKS);
            wmma::load_matrix_sync(fal, sp + (1 * BM + wm * 32 + 16) * SKS + ks * 16, SKS);
            wmma::mma_sync(acc1, fah, fbh, acc1);
            wmma::mma_sync(acc1, fah, fbl, acc1);
            wmma::mma_sync(acc1, fal, fbh, acc1);
        }
    }

    __pipeline_wait_prior(0);
    __syncthreads();
    float* stage = (float*)dynsm;   // 64 x 64 floats
    wmma::store_matrix_sync(stage + (wm * 32) * 64 + wn * 16, acc0, 64, wmma::mem_row_major);
    wmma::store_matrix_sync(stage + (wm * 32 + 16) * 64 + wn * 16, acc1, 64, wmma::mem_row_major);
    __syncthreads();

    #pragma unroll
    for (int i = 0; i < 4; i++) {
        int e   = tid + i * 256;
        int row = e >> 4;
        int c4  = (e & 15) * 4;
        int m   = mbase + row;
        int bb  = m >> 8;
        int ss  = m & 255;
        int col = nbase + c4;
        float4 v = *(float4*)(stage + row * 64 + c4);
        v.x += bias[col + 0];
        v.y += bias[col + 1];
        v.z += bias[col + 2];
        v.w += bias[col + 3];
        *(float4*)&g_xproj[(((size_t)gate * SEQ + ss) * BATCH + bb) * NH + col] = v;
    }
}

// ---------------- fp32 output GEMM (small) ----------------
__global__ __launch_bounds__(256) void out_gemm(const float* __restrict__ Wy,
                                                const float* __restrict__ by,
                                                float* __restrict__ out)
{
    __shared__ float As[TK][SROW];
    __shared__ float Bs[TK][SROW];
    const int tid = threadIdx.x;
    const int tx = tid & 15;
    const int ty = tid >> 4;
    const int mbase = blockIdx.y * TM;
    const int nbase = blockIdx.x * TN;
    const int lm = tid >> 2;
    const int lk = (tid & 3) << 2;

    float acc[4][4];
    #pragma unroll
    for (int i = 0; i < 4; i++) {
        #pragma unroll
        for (int j = 0; j < 4; j++) { acc[i][j] = 0.f; }
    }

    for (int kt = 0; kt < NH; kt += TK) {
        float4 av = *(const float4*)&g_h[(size_t)(mbase + lm) * NH + kt + lk];
        float4 bv = *(const float4*)&Wy [(size_t)(nbase + lm) * NH + kt + lk];
        __syncthreads();
        As[lk + 0][lm] = av.x; As[lk + 1][lm] = av.y;
        As[lk + 2][lm] = av.z; As[lk + 3][lm] = av.w;
        Bs[lk + 0][lm] = bv.x; Bs[lk + 1][lm] = bv.y;
        Bs[lk + 2][lm] = bv.z; Bs[lk + 3][lm] = bv.w;
        __syncthreads();
        #pragma unroll
        for (int k = 0; k < TK; k++) {
            float ar[4]; float br[4];
            #pragma unroll
            for (int i = 0; i < 4; i++) { ar[i] = As[k][(ty << 2) + i]; }
            #pragma unroll
            for (int j = 0; j < 4; j++) { br[j] = Bs[k][(tx << 2) + j]; }
            #pragma unroll
            for (int i = 0; i < 4; i++) {
                #pragma unroll
                for (int j = 0; j < 4; j++) { acc[i][j] = fmaf(ar[i], br[j], acc[i][j]); }
            }
        }
    }

    #pragma unroll
    for (int i = 0; i < 4; i++) {
        int m = mbase + (ty << 2) + i;
        int n0 = nbase + (tx << 2);
        #pragma unroll
        for (int j = 0; j < 4; j++) {
            out[(size_t)m * NOUT + n0 + j] = acc[i][j] + by[n0 + j];
        }
    }
}

__global__ __launch_bounds__(256) void copy_hc(float* __restrict__ out)
{
    const int idx = blockIdx.x * 256 + threadIdx.x;  // grid 512
    out[(size_t)BATCH * NOUT + idx]                      = g_h[idx];
    out[(size_t)BATCH * NOUT + (size_t)BATCH * NH + idx] = g_c[idx];
}

// ---------------------------------------------------------------------------
extern "C" void kernel_launch(void* const* d_in, const int* in_sizes, int n_in,
                              void* d_out, int out_size)
{
    const float* x_seq = (const float*)d_in[0];
    Ptr4 Wx; Ptr4 Bx; Ptr4 Wh;
    Wx.p[0] = (const float*)d_in[1];  Bx.p[0] = (const float*)d_in[2];  Wh.p[0] = (const float*)d_in[3];
    Wx.p[1] = (const float*)d_in[4];  Bx.p[1] = (const float*)d_in[5];  Wh.p[1] = (const float*)d_in[6];
    Wx.p[2] = (const float*)d_in[7];  Bx.p[2] = (const float*)d_in[8];  Wh.p[2] = (const float*)d_in[9];
    Wx.p[3] = (const float*)d_in[10]; Bx.p[3] = (const float*)d_in[11]; Wh.p[3] = (const float*)d_in[12];
    const float* Why_w = (const float*)d_in[13];
    const float* Why_b = (const float*)d_in[14];
    float* out = (float*)d_out;

    const int proj_smem = PSTAGES * PSTB * 2;   // 73728
    cudaFuncSetAttribute(rec_step,  cudaFuncAttributeMaxDynamicSharedMemorySize, REC_SMEM);
    cudaFuncSetAttribute(proj_gemm, cudaFuncAttributeMaxDynamicSharedMemorySize, proj_smem);

    fused_setup<<<65536, 256>>>(x_seq, Wh, Wx);

    proj_gemm<<<dim3(NH / BN, (BATCH * SEQ) / BM, 4), 256, proj_smem>>>(Bx);

    for (int t = 0; t < SEQ; t++) {
        rec_step<<<dim3(NH / RN, BATCH / 64), 512, REC_SMEM>>>(t);
    }

    out_gemm<<<dim3(NOUT / TN, BATCH / TM), 256>>>(Why_w, Why_b, out);
    copy_hc<<<512, 256>>>(out);
}

// round 12
// speedup vs baseline: 1.5174x; 1.5174x over previous
#include <cuda_runtime.h>
#include <cuda_bf16.h>
#include <mma.h>
#include <cuda_pipeline.h>

using namespace nvcuda;

#define BATCH 128
#define SEQ   256
#define NIN   512
#define NH    1024
#define NOUT  512

typedef __nv_bfloat16 bf16;

// proj GEMM tiling (unchanged, working)
#define BM 64
#define BN 64
#define BK 32
#define SKS 48
#define PSTAGES 3
#define PSTB (4 * BM * SKS)

// rec-step: block = 64 m x (16 n per gate x 4 gates), K-chunk 64
#define RN 16
#define RKC 64
#define RNCH (NH / RKC)        /* 16 */
#define RSTG 3
#define STG_BYTES 32768        /* A hi/lo 8KB each + 8 B planes x 2KB */
#define TILE_BASE 1024
#define REC_SMEM (TILE_BASE + RSTG * STG_BYTES)   /* 99328 */
#define TX_BYTES 32768

// fp32 out_gemm tiling
#define TM 64
#define TN 64
#define TK 16
#define SROW 68

// ---------------- scratch (device globals) ----------------
__device__ float g_xproj[(size_t)4 * SEQ * BATCH * NH];
__device__ float g_h[BATCH * NH];
__device__ float g_c[BATCH * NH];
// h in K-chunked, SW128-pre-swizzled layout: [kc][m 0..127][64] (16KB per kc)
__device__ bf16  g_hA_hi[BATCH * NH];
__device__ bf16  g_hA_lo[BATCH * NH];
__device__ bf16  g_hB_hi[BATCH * NH];
__device__ bf16  g_hB_lo[BATCH * NH];
// Wh in K-chunked, SW128-pre-swizzled layout: [gate][kc][n 0..1023][64]
__device__ bf16  g_Whr_hi[(size_t)4 * NH * NH];
__device__ bf16  g_Whr_lo[(size_t)4 * NH * NH];
__device__ bf16  g_Wx_hi[(size_t)4 * NH * NIN];
__device__ bf16  g_Wx_lo[(size_t)4 * NH * NIN];
__device__ bf16  g_x_hi[(size_t)BATCH * SEQ * NIN];
__device__ bf16  g_x_lo[(size_t)BATCH * SEQ * NIN];

struct Ptr4 { const float* p[4]; };

__device__ __forceinline__ float fast_sigmoid(float x) { return 1.f / (1.f + __expf(-x)); }
__device__ __forceinline__ float fast_tanh(float x)    { return 2.f * fast_sigmoid(2.f * x) - 1.f; }
__device__ __forceinline__ uint32_t swz128(uint32_t o) { return o ^ ((o >> 3) & 0x70u); }

// ---------------- asm helpers (spaced-brace style, proven to compile) -------
__device__ __forceinline__ void mbar_init(uint32_t a, uint32_t cnt)
{
    asm volatile("mbarrier.init.shared.b64 [ %0 ], %1;" :: "r"(a), "r"(cnt) : "memory");
}
__device__ __forceinline__ void mbar_expect_tx(uint32_t a, uint32_t bytes)
{
    asm volatile("mbarrier.arrive.expect_tx.shared.b64 _, [ %0 ], %1;"
                 :: "r"(a), "r"(bytes) : "memory");
}
__device__ __forceinline__ void mbar_wait(uint32_t a, uint32_t parity)
{
    asm volatile(
        "{ .reg .pred P1; "
        "LAB_%=: mbarrier.try_wait.parity.acquire.cta.shared::cta.b64 P1, [ %0 ], %1; "
        "@P1 bra DONE_%=; "
        "bra LAB_%=; "
        "DONE_%=: }"
        :: "r"(a), "r"(parity) : "memory");
}
__device__ __forceinline__ void bulk_copy(uint32_t dst, const void* src, uint32_t bytes,
                                          uint32_t mbar)
{
    asm volatile(
        "cp.async.bulk.shared::cluster.global.mbarrier::complete_tx::bytes "
        "[ %0 ], [ %1 ], %2, [ %3 ];"
        :: "r"(dst), "l"(src), "r"(bytes), "r"(mbar) : "memory");
}
__device__ __forceinline__ void fence_async_shared()
{
    asm volatile("fence.proxy.async.shared::cta;" ::: "memory");
}
__device__ __forceinline__ void ldsm4(uint32_t* r, uint32_t addr)
{
    asm volatile("ldmatrix.sync.aligned.m8n8.x4.shared.b16 { %0, %1, %2, %3 }, [ %4 ];"
                 : "=r"(r[0]), "=r"(r[1]), "=r"(r[2]), "=r"(r[3]) : "r"(addr));
}
__device__ __forceinline__ void mma_bf16(float* c, const uint32_t* a, uint32_t b0, uint32_t b1)
{
    asm volatile(
        "mma.sync.aligned.m16n8k16.row.col.f32.bf16.bf16.f32 "
        "{ %0, %1, %2, %3 }, { %4, %5, %6, %7 }, { %8, %9 }, { %0, %1, %2, %3 };"
        : "+f"(c[0]), "+f"(c[1]), "+f"(c[2]), "+f"(c[3])
        : "r"(a[0]), "r"(a[1]), "r"(a[2]), "r"(a[3]), "r"(b0), "r"(b1));
}

// ---------------- fused setup: init + all splits in ONE launch ----------------
__global__ __launch_bounds__(256) void fused_setup(const float* __restrict__ x,
                                                   Ptr4 Wh, Ptr4 Wx)
{
    const size_t idx = (size_t)blockIdx.x * 256 + threadIdx.x;
    {
        float v = x[idx];
        bf16 hv = __float2bfloat16_rn(v);
        g_x_hi[idx] = hv;
        g_x_lo[idx] = __float2bfloat16_rn(v - __bfloat162float(hv));
    }
    if (idx < (size_t)4 * NH * NH) {
        int gate = (int)(idx >> 20);
        uint32_t r = (uint32_t)(idx & ((1u << 20) - 1));
        float v = Wh.p[gate][r];
        bf16 hv = __float2bfloat16_rn(v);
        bf16 lv = __float2bfloat16_rn(v - __bfloat162float(hv));
        uint32_t n = r >> 10;
        uint32_t k = r & 1023u;
        uint32_t kc = k >> 6;
        uint32_t col = k & 63u;
        size_t byte = (size_t)gate * 2097152u + (size_t)kc * 131072u
                    + swz128(n * 128u + col * 2u);
        *(bf16*)((char*)g_Whr_hi + byte) = hv;
        *(bf16*)((char*)g_Whr_lo + byte) = lv;
    }
    if (idx < (size_t)4 * NH * NIN) {
        int gate = (int)(idx >> 19);
        float v = Wx.p[gate][idx & ((1u << 19) - 1)];
        bf16 hv = __float2bfloat16_rn(v);
        g_Wx_hi[idx] = hv;
        g_Wx_lo[idx] = __float2bfloat16_rn(v - __bfloat162float(hv));
    }
    if (idx < (size_t)BATCH * NH) {
        g_h[idx] = 0.f;
        g_c[idx] = 0.f;
        g_hA_hi[idx] = __float2bfloat16_rn(0.f);
        g_hA_lo[idx] = __float2bfloat16_rn(0.f);
    }
}

// ---------------- fused recurrent step (large bulk copies + asm MMA) --------
// grid (NH/RN=64, BATCH/64=2) = 128 blocks, 512 threads (16 warps).
// Stage (32KB): [0,8K) A hi (64 m x 128B swz), [8K,16K) A lo,
// [16K,32K) B: plane p, gate g at 16K + p*8K + g*2K (16 n x 128B swz).
// Warp (gp=warp>>2 gate, wq=warp&3 m-quarter) computes 16m x 16n in registers.
__global__ __launch_bounds__(512) void rec_step(int t)
{
    extern __shared__ __align__(128) unsigned char dynsm[];
    const uint32_t smem_u32 = (uint32_t)__cvta_generic_to_shared(dynsm);

    const int par = t & 1;
    const bf16* __restrict__ hin_hi = par ? g_hB_hi : g_hA_hi;
    const bf16* __restrict__ hin_lo = par ? g_hB_lo : g_hA_lo;
    bf16* __restrict__ hout_hi = par ? g_hA_hi : g_hB_hi;
    bf16* __restrict__ hout_lo = par ? g_hA_lo : g_hB_lo;

    const int tid   = threadIdx.x;
    const int warp  = tid >> 5;
    const int lane  = tid & 31;
    const int nbase = blockIdx.x * RN;
    const int mbase = blockIdx.y * 64;

    if (tid == 0) {
        mbar_init(smem_u32 + 0, 1);
        mbar_init(smem_u32 + 8, 1);
        mbar_init(smem_u32 + 16, 1);
        fence_async_shared();
    }

    // epilogue operand prefetch (independent of GEMM)
    const int erow  = tid >> 3;        // m 0..63
    const int ecol2 = (tid & 7) * 2;   // n-pair
    const int em = mbase + erow;
    const int en = nbase + ecol2;
    const size_t BH = (size_t)BATCH * NH;
    float2 xf = *(const float2*)&g_xproj[((size_t)(0 * SEQ) + t) * BH + (size_t)em * NH + en];
    float2 xi = *(const float2*)&g_xproj[((size_t)(1 * SEQ) + t) * BH + (size_t)em * NH + en];
    float2 xg = *(const float2*)&g_xproj[((size_t)(2 * SEQ) + t) * BH + (size_t)em * NH + en];
    float2 xo = *(const float2*)&g_xproj[((size_t)(3 * SEQ) + t) * BH + (size_t)em * NH + en];
    float2 cv = *(const float2*)&g_c[(size_t)em * NH + en];

    // bulk-copy sources (kc strides: A 16384 B, Wh 131072 B)
    const char* srcA0 = (const char*)hin_hi + (size_t)mbase * 128;
    const char* srcA1 = (const char*)hin_lo + (size_t)mbase * 128;
    const char* srcB[8];
    #pragma unroll
    for (int j = 0; j < 8; j++) {
        int p = j >> 2;
        int g = j & 3;
        srcB[j] = (const char*)(p ? g_Whr_lo : g_Whr_hi)
                + (size_t)g * 2097152u + (size_t)nbase * 128;
    }

    __syncthreads();   // mbarriers visible

    // prologue: chunks 0, 1
    if (tid == 0) {
        #pragma unroll
        for (int s = 0; s < RSTG - 1; s++) {
            const uint32_t mb = smem_u32 + s * 8;
            const uint32_t dst = smem_u32 + TILE_BASE + s * STG_BYTES;
            mbar_expect_tx(mb, TX_BYTES);
            bulk_copy(dst,         srcA0 + (size_t)s * 16384, 8192u, mb);
            bulk_copy(dst + 8192,  srcA1 + (size_t)s * 16384, 8192u, mb);
            #pragma unroll
            for (int j = 0; j < 8; j++) {
                bulk_copy(dst + 16384 + (j >> 2) * 8192 + (j & 3) * 2048,
                          srcB[j] + (size_t)s * 131072, 2048u, mb);
            }
        }
    }

    const int gp = warp >> 2;   // gate
    const int wq = warp & 3;    // m-quarter
    const int frow  = lane & 15;
    const int fhalf = (lane >> 4) << 4;   // 0 or 16 bytes

    float acc0[4];
    float acc1[4];
    #pragma unroll
    for (int q = 0; q < 4; q++) { acc0[q] = 0.f; acc1[q] = 0.f; }

    for (int c = 0; c < RNCH; c++) {
        mbar_wait(smem_u32 + (c % RSTG) * 8, (uint32_t)((c / RSTG) & 1));
        __syncthreads();   // readers of stage (c-1) done -> safe to refill (c+2)

        const int cn = c + RSTG - 1;
        if (cn < RNCH && tid == 0) {
            const uint32_t mb = smem_u32 + (cn % RSTG) * 8;
            const uint32_t dst = smem_u32 + TILE_BASE + (cn % RSTG) * STG_BYTES;
            mbar_expect_tx(mb, TX_BYTES);
            fence_async_shared();
            bulk_copy(dst,         srcA0 + (size_t)cn * 16384, 8192u, mb);
            bulk_copy(dst + 8192,  srcA1 + (size_t)cn * 16384, 8192u, mb);
            #pragma unroll
            for (int j = 0; j < 8; j++) {
                bulk_copy(dst + 16384 + (j >> 2) * 8192 + (j & 3) * 2048,
                          srcB[j] + (size_t)cn * 131072, 2048u, mb);
            }
        }

        const uint32_t su = smem_u32 + TILE_BASE + (uint32_t)((c % RSTG) * STG_BYTES);
        #pragma unroll
        for (int ks = 0; ks < 4; ks++) {
            const uint32_t oa = (uint32_t)((wq * 16 + frow) * 128 + ks * 32 + fhalf);
            const uint32_t ob = (uint32_t)(frow * 128 + ks * 32 + fhalf);
            uint32_t ah[4]; uint32_t al[4]; uint32_t bh[4]; uint32_t bl[4];
            ldsm4(ah, su + swz128(oa));
            ldsm4(al, su + 8192u + swz128(oa));
            ldsm4(bh, su + 16384u + (uint32_t)(gp * 2048) + swz128(ob));
            ldsm4(bl, su + 24576u + (uint32_t)(gp * 2048) + swz128(ob));

            mma_bf16(acc0, ah, bh[0], bh[2]);
            mma_bf16(acc0, ah, bl[0], bl[2]);
            mma_bf16(acc0, al, bh[0], bh[2]);

            mma_bf16(acc1, ah, bh[1], bh[3]);
            mma_bf16(acc1, ah, bl[1], bl[3]);
            mma_bf16(acc1, al, bh[1], bh[3]);
        }
    }

    __syncthreads();
    // overlay fp32 staging on pipeline buffers: stage[gate][m 0..63][n 0..15]
    float* stage = (float*)(dynsm + TILE_BASE);
    {
        const int row  = lane >> 2;
        const int colp = (lane & 3) * 2;
        float* b0 = stage + (gp * 64 + wq * 16 + row) * RN;
        float* b8 = stage + (gp * 64 + wq * 16 + row + 8) * RN;
        b0[colp]     = acc0[0];
        b0[colp + 1] = acc0[1];
        b8[colp]     = acc0[2];
        b8[colp + 1] = acc0[3];
        b0[colp + 8]     = acc1[0];
        b0[colp + 9]     = acc1[1];
        b8[colp + 8]     = acc1[2];
        b8[colp + 9]     = acc1[3];
    }
    __syncthreads();

    // cell update: 64m x 16n = 1024 cells, 2 consecutive n per thread
    {
        float2 pf = *(float2*)(stage + (0 * 64 + erow) * RN + ecol2);
        float2 pi = *(float2*)(stage + (1 * 64 + erow) * RN + ecol2);
        float2 pg = *(float2*)(stage + (2 * 64 + erow) * RN + ecol2);
        float2 po = *(float2*)(stage + (3 * 64 + erow) * RN + ecol2);

        float hv[2];
        float cn2[2];
        float pfv[2]; float piv[2]; float pgv[2]; float pov[2];
        float xfv[2]; float xiv[2]; float xgv[2]; float xov[2];
        float ccv[2];
        pfv[0]=pf.x; pfv[1]=pf.y;
        piv[0]=pi.x; piv[1]=pi.y;
        pgv[0]=pg.x; pgv[1]=pg.y;
        pov[0]=po.x; pov[1]=po.y;
        xfv[0]=xf.x; xfv[1]=xf.y;
        xiv[0]=xi.x; xiv[1]=xi.y;
        xgv[0]=xg.x; xgv[1]=xg.y;
        xov[0]=xo.x; xov[1]=xo.y;
        ccv[0]=cv.x; ccv[1]=cv.y;

        #pragma unroll
        for (int j = 0; j < 2; j++) {
            float fg = fast_sigmoid(pfv[j] + xfv[j]);
            float ig = fast_sigmoid(piv[j] + xiv[j]);
            float gg = fast_tanh(pgv[j] + xgv[j]);
            float og = fast_sigmoid(pov[j] + xov[j]);
            float c2 = fg * ccv[j] + ig * gg;
            cn2[j] = c2;
            hv[j] = og * fast_tanh(c2);
        }

        *(float2*)&g_c[(size_t)em * NH + en] = make_float2(cn2[0], cn2[1]);
        *(float2*)&g_h[(size_t)em * NH + en] = make_float2(hv[0], hv[1]);

        __nv_bfloat162 hh = __floats2bfloat162_rn(hv[0], hv[1]);
        float l0 = hv[0] - __bfloat162float(__low2bfloat16(hh));
        float l1 = hv[1] - __bfloat162float(__high2bfloat16(hh));
        // write next-step h in K-chunked pre-swizzled layout
        const uint32_t kc  = (uint32_t)(en >> 6);
        const uint32_t col = (uint32_t)(en & 63);
        const size_t byte = (size_t)kc * 16384u + swz128((uint32_t)em * 128u + col * 2u);
        *(__nv_bfloat162*)((char*)hout_hi + byte) = hh;
        *(__nv_bfloat162*)((char*)hout_lo + byte) = __floats2bfloat162_rn(l0, l1);
    }
}

// ---------------- bf16x3 input-projection GEMM (cp.async 3-stage, unchanged) --
__global__ __launch_bounds__(256) void proj_gemm(Ptr4 Bias)
{
    extern __shared__ __align__(16) unsigned char dynsm[];
    bf16* stg = (bf16*)dynsm;

    const int gate = blockIdx.z;
    const bf16* __restrict__ Bhi = g_Wx_hi + (size_t)gate * NH * NIN;
    const bf16* __restrict__ Blo = g_Wx_lo + (size_t)gate * NH * NIN;
    const float* __restrict__ bias = Bias.p[gate];

    const int tid   = threadIdx.x;
    const int warp  = tid >> 5;
    const int wm    = warp >> 2;
    const int wn    = warp & 3;
    const int mbase = blockIdx.y * BM;
    const int nbase = blockIdx.x * BN;

    const bf16* gsrc[4];
    int soff[4];
    #pragma unroll
    for (int l = 0; l < 4; l++) {
        int idx = l * 256 + tid;
        int p   = idx >> 8;
        int w   = idx & 255;
        int row = w >> 2;
        int q   = (w & 3) * 8;
        soff[l] = (p * BM + row) * SKS + q;
        if (p == 0) {
            gsrc[l] = g_x_hi + (size_t)(mbase + row) * NIN + q;
        } else if (p == 1) {
            gsrc[l] = g_x_lo + (size_t)(mbase + row) * NIN + q;
        } else if (p == 2) {
            gsrc[l] = Bhi + (size_t)(nbase + row) * NIN + q;
        } else {
            gsrc[l] = Blo + (size_t)(nbase + row) * NIN + q;
        }
    }

    wmma::fragment<wmma::accumulator, 16, 16, 16, float> acc0;
    wmma::fragment<wmma::accumulator, 16, 16, 16, float> acc1;
    wmma::fill_fragment(acc0, 0.0f);
    wmma::fill_fragment(acc1, 0.0f);

    const int NC = NIN / BK;   // 16

    #pragma unroll
    for (int s = 0; s < PSTAGES - 1; s++) {
        const int ko = s * BK;
        #pragma unroll
        for (int l = 0; l < 4; l++) {
            __pipeline_memcpy_async(stg + s * PSTB + soff[l], gsrc[l] + ko, 16);
        }
        __pipeline_commit();
    }

    for (int c = 0; c < NC; c++) {
        __pipeline_wait_prior(PSTAGES - 2);
        __syncthreads();

        const int cn = c + PSTAGES - 1;
        if (cn < NC) {
            const int ko = cn * BK;
            const int ds = cn % PSTAGES;
            #pragma unroll
            for (int l = 0; l < 4; l++) {
                __pipeline_memcpy_async(stg + ds * PSTB + soff[l], gsrc[l] + ko, 16);
            }
        }
        __pipeline_commit();

        bf16* sp = stg + (c % PSTAGES) * PSTB;
        #pragma unroll
        for (int ks = 0; ks < 2; ks++) {
            wmma::fragment<wmma::matrix_b, 16, 16, 16, bf16, wmma::col_major> fbh;
            wmma::fragment<wmma::matrix_b, 16, 16, 16, bf16, wmma::col_major> fbl;
            wmma::load_matrix_sync(fbh, sp + (2 * BM + wn * 16) * SKS + ks * 16, SKS);
            wmma::load_matrix_sync(fbl, sp + (3 * BM + wn * 16) * SKS + ks * 16, SKS);

            wmma::fragment<wmma::matrix_a, 16, 16, 16, bf16, wmma::row_major> fah;
            wmma::fragment<wmma::matrix_a, 16, 16, 16, bf16, wmma::row_major> fal;
            wmma::load_matrix_sync(fah, sp + (0 * BM + wm * 32) * SKS + ks * 16, SKS);
            wmma::load_matrix_sync(fal, sp + (1 * BM + wm * 32) * SKS + ks * 16, SKS);
            wmma::mma_sync(acc0, fah, fbh, acc0);
            wmma::mma_sync(acc0, fah, fbl, acc0);
            wmma::mma_sync(acc0, fal, fbh, acc0);

            wmma::load_matrix_sync(fah, sp + (0 * BM + wm * 32 + 16) * SKS + ks * 16, SKS);
            wmma::load_matrix_sync(fal, sp + (1 * BM + wm * 32 + 16) * SKS + ks * 16, SKS);
            wmma::mma_sync(acc1, fah, fbh, acc1);
            wmma::mma_sync(acc1, fah, fbl, acc1);
            wmma::mma_sync(acc1, fal, fbh, acc1);
        }
    }

    __pipeline_wait_prior(0);
    __syncthreads();
    float* stage = (float*)dynsm;   // 64 x 64 floats
    wmma::store_matrix_sync(stage + (wm * 32) * 64 + wn * 16, acc0, 64, wmma::mem_row_major);
    wmma::store_matrix_sync(stage + (wm * 32 + 16) * 64 + wn * 16, acc1, 64, wmma::mem_row_major);
    __syncthreads();

    #pragma unroll
    for (int i = 0; i < 4; i++) {
        int e   = tid + i * 256;
        int row = e >> 4;
        int c4  = (e & 15) * 4;
        int m   = mbase + row;
        int bb  = m >> 8;
        int ss  = m & 255;
        int col = nbase + c4;
        float4 v = *(float4*)(stage + row * 64 + c4);
        v.x += bias[col + 0];
        v.y += bias[col + 1];
        v.z += bias[col + 2];
        v.w += bias[col + 3];
        *(float4*)&g_xproj[(((size_t)gate * SEQ + ss) * BATCH + bb) * NH + col] = v;
    }
}

// ---------------- fp32 output GEMM (small) ----------------
__global__ __launch_bounds__(256) void out_gemm(const float* __restrict__ Wy,
                                                const float* __restrict__ by,
                                                float* __restrict__ out)
{
    __shared__ float As[TK][SROW];
    __shared__ float Bs[TK][SROW];
    const int tid = threadIdx.x;
    const int tx = tid & 15;
    const int ty = tid >> 4;
    const int mbase = blockIdx.y * TM;
    const int nbase = blockIdx.x * TN;
    const int lm = tid >> 2;
    const int lk = (tid & 3) << 2;

    float acc[4][4];
    #pragma unroll
    for (int i = 0; i < 4; i++) {
        #pragma unroll
        for (int j = 0; j < 4; j++) { acc[i][j] = 0.f; }
    }

    for (int kt = 0; kt < NH; kt += TK) {
        float4 av = *(const float4*)&g_h[(size_t)(mbase + lm) * NH + kt + lk];
        float4 bv = *(const float4*)&Wy [(size_t)(nbase + lm) * NH + kt + lk];
        __syncthreads();
        As[lk + 0][lm] = av.x; As[lk + 1][lm] = av.y;
        As[lk + 2][lm] = av.z; As[lk + 3][lm] = av.w;
        Bs[lk + 0][lm] = bv.x; Bs[lk + 1][lm] = bv.y;
        Bs[lk + 2][lm] = bv.z; Bs[lk + 3][lm] = bv.w;
        __syncthreads();
        #pragma unroll
        for (int k = 0; k < TK; k++) {
            float ar[4]; float br[4];
            #pragma unroll
            for (int i = 0; i < 4; i++) { ar[i] = As[k][(ty << 2) + i]; }
            #pragma unroll
            for (int j = 0; j < 4; j++) { br[j] = Bs[k][(tx << 2) + j]; }
            #pragma unroll
            for (int i = 0; i < 4; i++) {
                #pragma unroll
                for (int j = 0; j < 4; j++) { acc[i][j] = fmaf(ar[i], br[j], acc[i][j]); }
            }
        }
    }

    #pragma unroll
    for (int i = 0; i < 4; i++) {
        int m = mbase + (ty << 2) + i;
        int n0 = nbase + (tx << 2);
        #pragma unroll
        for (int j = 0; j < 4; j++) {
            out[(size_t)m * NOUT + n0 + j] = acc[i][j] + by[n0 + j];
        }
    }
}

__global__ __launch_bounds__(256) void copy_hc(float* __restrict__ out)
{
    const int idx = blockIdx.x * 256 + threadIdx.x;  // grid 512
    out[(size_t)BATCH * NOUT + idx]                      = g_h[idx];
    out[(size_t)BATCH * NOUT + (size_t)BATCH * NH + idx] = g_c[idx];
}

// ---------------------------------------------------------------------------
extern "C" void kernel_launch(void* const* d_in, const int* in_sizes, int n_in,
                              void* d_out, int out_size)
{
    const float* x_seq = (const float*)d_in[0];
    Ptr4 Wx; Ptr4 Bx; Ptr4 Wh;
    Wx.p[0] = (const float*)d_in[1];  Bx.p[0] = (const float*)d_in[2];  Wh.p[0] = (const float*)d_in[3];
    Wx.p[1] = (const float*)d_in[4];  Bx.p[1] = (const float*)d_in[5];  Wh.p[1] = (const float*)d_in[6];
    Wx.p[2] = (const float*)d_in[7];  Bx.p[2] = (const float*)d_in[8];  Wh.p[2] = (const float*)d_in[9];
    Wx.p[3] = (const float*)d_in[10]; Bx.p[3] = (const float*)d_in[11]; Wh.p[3] = (const float*)d_in[12];
    const float* Why_w = (const float*)d_in[13];
    const float* Why_b = (const float*)d_in[14];
    float* out = (float*)d_out;

    const int proj_smem = PSTAGES * PSTB * 2;   // 73728
    cudaFuncSetAttribute(rec_step,  cudaFuncAttributeMaxDynamicSharedMemorySize, REC_SMEM);
    cudaFuncSetAttribute(proj_gemm, cudaFuncAttributeMaxDynamicSharedMemorySize, proj_smem);

    fused_setup<<<65536, 256>>>(x_seq, Wh, Wx);

    proj_gemm<<<dim3(NH / BN, (BATCH * SEQ) / BM, 4), 256, proj_smem>>>(Bx);

    for (int t = 0; t < SEQ; t++) {
        rec_step<<<dim3(NH / RN, BATCH / 64), 512, REC_SMEM>>>(t);
    }

    out_gemm<<<dim3(NOUT / TN, BATCH / TM), 256>>>(Why_w, Why_b, out);
    copy_hc<<<512, 256>>>(out);
}

// round 13
// speedup vs baseline: 1.5415x; 1.0159x over previous
#include <cuda_runtime.h>
#include <cuda_bf16.h>
#include <mma.h>
#include <cuda_pipeline.h>

using namespace nvcuda;

#define BATCH 128
#define SEQ   256
#define NIN   512
#define NH    1024
#define NOUT  512

typedef __nv_bfloat16 bf16;

// proj GEMM tiling (unchanged, working)
#define BM 64
#define BN 64
#define BK 32
#define SKS 48
#define PSTAGES 3
#define PSTB (4 * BM * SKS)

// rec-step: block = 32 m x (16 n per gate x 4 gates), K-chunk 64
#define RN 16
#define RM 32
#define RKC 64
#define RNCH (NH / RKC)        /* 16 */
#define RSTG 3
#define STG_BYTES 24576        /* A hi/lo 4KB each + 8 B planes x 2KB */
#define TILE_BASE 1024
#define REC_SMEM (TILE_BASE + RSTG * STG_BYTES)   /* 74752 -> 2 CTAs/SM */
#define TX_BYTES 24576

// fp32 out_gemm tiling
#define TM 64
#define TN 64
#define TK 16
#define SROW 68

// ---------------- scratch (device globals) ----------------
__device__ float g_xproj[(size_t)4 * SEQ * BATCH * NH];
__device__ float g_h[BATCH * NH];
__device__ float g_c[BATCH * NH];
// h in K-chunked, SW128-pre-swizzled layout: [kc][m 0..127][64] (16KB per kc)
__device__ bf16  g_hA_hi[BATCH * NH];
__device__ bf16  g_hA_lo[BATCH * NH];
__device__ bf16  g_hB_hi[BATCH * NH];
__device__ bf16  g_hB_lo[BATCH * NH];
// Wh in K-chunked, SW128-pre-swizzled layout: [gate][kc][n 0..1023][64]
__device__ bf16  g_Whr_hi[(size_t)4 * NH * NH];
__device__ bf16  g_Whr_lo[(size_t)4 * NH * NH];
__device__ bf16  g_Wx_hi[(size_t)4 * NH * NIN];
__device__ bf16  g_Wx_lo[(size_t)4 * NH * NIN];
__device__ bf16  g_x_hi[(size_t)BATCH * SEQ * NIN];
__device__ bf16  g_x_lo[(size_t)BATCH * SEQ * NIN];

struct Ptr4 { const float* p[4]; };

__device__ __forceinline__ float fast_sigmoid(float x) { return 1.f / (1.f + __expf(-x)); }
__device__ __forceinline__ float fast_tanh(float x)    { return 2.f * fast_sigmoid(2.f * x) - 1.f; }
__device__ __forceinline__ uint32_t swz128(uint32_t o) { return o ^ ((o >> 3) & 0x70u); }

// ---------------- asm helpers (spaced-brace style, proven to compile) -------
__device__ __forceinline__ void mbar_init(uint32_t a, uint32_t cnt)
{
    asm volatile("mbarrier.init.shared.b64 [ %0 ], %1;" :: "r"(a), "r"(cnt) : "memory");
}
__device__ __forceinline__ void mbar_expect_tx(uint32_t a, uint32_t bytes)
{
    asm volatile("mbarrier.arrive.expect_tx.shared.b64 _, [ %0 ], %1;"
                 :: "r"(a), "r"(bytes) : "memory");
}
__device__ __forceinline__ void mbar_wait(uint32_t a, uint32_t parity)
{
    asm volatile(
        "{ .reg .pred P1; "
        "LAB_%=: mbarrier.try_wait.parity.acquire.cta.shared::cta.b64 P1, [ %0 ], %1; "
        "@P1 bra DONE_%=; "
        "bra LAB_%=; "
        "DONE_%=: }"
        :: "r"(a), "r"(parity) : "memory");
}
__device__ __forceinline__ void bulk_copy(uint32_t dst, const void* src, uint32_t bytes,
                                          uint32_t mbar)
{
    asm volatile(
        "cp.async.bulk.shared::cluster.global.mbarrier::complete_tx::bytes "
        "[ %0 ], [ %1 ], %2, [ %3 ];"
        :: "r"(dst), "l"(src), "r"(bytes), "r"(mbar) : "memory");
}
__device__ __forceinline__ void fence_async_shared()
{
    asm volatile("fence.proxy.async.shared::cta;" ::: "memory");
}
__device__ __forceinline__ void ldsm4(uint32_t* r, uint32_t addr)
{
    asm volatile("ldmatrix.sync.aligned.m8n8.x4.shared.b16 { %0, %1, %2, %3 }, [ %4 ];"
                 : "=r"(r[0]), "=r"(r[1]), "=r"(r[2]), "=r"(r[3]) : "r"(addr));
}
__device__ __forceinline__ void mma_bf16(float* c, const uint32_t* a, uint32_t b0, uint32_t b1)
{
    asm volatile(
        "mma.sync.aligned.m16n8k16.row.col.f32.bf16.bf16.f32 "
        "{ %0, %1, %2, %3 }, { %4, %5, %6, %7 }, { %8, %9 }, { %0, %1, %2, %3 };"
        : "+f"(c[0]), "+f"(c[1]), "+f"(c[2]), "+f"(c[3])
        : "r"(a[0]), "r"(a[1]), "r"(a[2]), "r"(a[3]), "r"(b0), "r"(b1));
}

// ---------------- fused setup: init + all splits in ONE launch ----------------
__global__ __launch_bounds__(256) void fused_setup(const float* __restrict__ x,
                                                   Ptr4 Wh, Ptr4 Wx)
{
    const size_t idx = (size_t)blockIdx.x * 256 + threadIdx.x;
    {
        float v = x[idx];
        bf16 hv = __float2bfloat16_rn(v);
        g_x_hi[idx] = hv;
        g_x_lo[idx] = __float2bfloat16_rn(v - __bfloat162float(hv));
    }
    if (idx < (size_t)4 * NH * NH) {
        int gate = (int)(idx >> 20);
        uint32_t r = (uint32_t)(idx & ((1u << 20) - 1));
        float v = Wh.p[gate][r];
        bf16 hv = __float2bfloat16_rn(v);
        bf16 lv = __float2bfloat16_rn(v - __bfloat162float(hv));
        uint32_t n = r >> 10;
        uint32_t k = r & 1023u;
        uint32_t kc = k >> 6;
        uint32_t col = k & 63u;
        size_t byte = (size_t)gate * 2097152u + (size_t)kc * 131072u
                    + swz128(n * 128u + col * 2u);
        *(bf16*)((char*)g_Whr_hi + byte) = hv;
        *(bf16*)((char*)g_Whr_lo + byte) = lv;
    }
    if (idx < (size_t)4 * NH * NIN) {
        int gate = (int)(idx >> 19);
        float v = Wx.p[gate][idx & ((1u << 19) - 1)];
        bf16 hv = __float2bfloat16_rn(v);
        g_Wx_hi[idx] = hv;
        g_Wx_lo[idx] = __float2bfloat16_rn(v - __bfloat162float(hv));
    }
    if (idx < (size_t)BATCH * NH) {
        g_h[idx] = 0.f;
        g_c[idx] = 0.f;
        g_hA_hi[idx] = __float2bfloat16_rn(0.f);
        g_hA_lo[idx] = __float2bfloat16_rn(0.f);
    }
}

// ---------------- fused recurrent step (32m tile, 2 CTAs/SM) ----------------
// grid (NH/RN=64, BATCH/RM=4) = 256 blocks, 256 threads (8 warps).
// Stage (24KB): [0,4K) A hi (32 m x 128B swz), [4K,8K) A lo,
// [8K,24K) B: plane p at 8K + p*8K, gate g at +g*2K (16 n x 128B swz).
// Warp (gp=warp>>1 gate, wq=warp&1 m-half) computes 16m x 16n in registers.
__global__ __launch_bounds__(256) void rec_step(int t)
{
    extern __shared__ __align__(128) unsigned char dynsm[];
    const uint32_t smem_u32 = (uint32_t)__cvta_generic_to_shared(dynsm);

    const int par = t & 1;
    const bf16* __restrict__ hin_hi = par ? g_hB_hi : g_hA_hi;
    const bf16* __restrict__ hin_lo = par ? g_hB_lo : g_hA_lo;
    bf16* __restrict__ hout_hi = par ? g_hA_hi : g_hB_hi;
    bf16* __restrict__ hout_lo = par ? g_hA_lo : g_hB_lo;

    const int tid   = threadIdx.x;
    const int warp  = tid >> 5;
    const int lane  = tid & 31;
    const int nbase = blockIdx.x * RN;
    const int mbase = blockIdx.y * RM;

    if (tid == 0) {
        mbar_init(smem_u32 + 0, 1);
        mbar_init(smem_u32 + 8, 1);
        mbar_init(smem_u32 + 16, 1);
        fence_async_shared();
    }

    // epilogue operand prefetch (independent of GEMM): 512 cells, 2 n/thread
    const int erow  = tid >> 3;        // m 0..31
    const int ecol2 = (tid & 7) * 2;   // n-pair
    const int em = mbase + erow;
    const int en = nbase + ecol2;
    const size_t BH = (size_t)BATCH * NH;
    float2 xf = *(const float2*)&g_xproj[((size_t)(0 * SEQ) + t) * BH + (size_t)em * NH + en];
    float2 xi = *(const float2*)&g_xproj[((size_t)(1 * SEQ) + t) * BH + (size_t)em * NH + en];
    float2 xg = *(const float2*)&g_xproj[((size_t)(2 * SEQ) + t) * BH + (size_t)em * NH + en];
    float2 xo = *(const float2*)&g_xproj[((size_t)(3 * SEQ) + t) * BH + (size_t)em * NH + en];
    float2 cv = *(const float2*)&g_c[(size_t)em * NH + en];

    // bulk-copy sources (kc strides: A 16384 B, Wh 131072 B)
    const char* srcA0 = (const char*)hin_hi + (size_t)mbase * 128;
    const char* srcA1 = (const char*)hin_lo + (size_t)mbase * 128;
    const char* srcB[8];
    #pragma unroll
    for (int j = 0; j < 8; j++) {
        int p = j >> 2;
        int g = j & 3;
        srcB[j] = (const char*)(p ? g_Whr_lo : g_Whr_hi)
                + (size_t)g * 2097152u + (size_t)nbase * 128;
    }

    __syncthreads();   // mbarriers visible

    // prologue: chunks 0, 1
    if (tid == 0) {
        #pragma unroll
        for (int s = 0; s < RSTG - 1; s++) {
            const uint32_t mb = smem_u32 + s * 8;
            const uint32_t dst = smem_u32 + TILE_BASE + s * STG_BYTES;
            mbar_expect_tx(mb, TX_BYTES);
            bulk_copy(dst,        srcA0 + (size_t)s * 16384, 4096u, mb);
            bulk_copy(dst + 4096, srcA1 + (size_t)s * 16384, 4096u, mb);
            #pragma unroll
            for (int j = 0; j < 8; j++) {
                bulk_copy(dst + 8192 + (j >> 2) * 8192 + (j & 3) * 2048,
                          srcB[j] + (size_t)s * 131072, 2048u, mb);
            }
        }
    }

    const int gp = warp >> 1;   // gate 0..3
    const int wq = warp & 1;    // m-half 0..1
    const int frow  = lane & 15;
    const int fhalf = (lane >> 4) << 4;   // 0 or 16 bytes

    float acc0[4];
    float acc1[4];
    #pragma unroll
    for (int q = 0; q < 4; q++) { acc0[q] = 0.f; acc1[q] = 0.f; }

    for (int c = 0; c < RNCH; c++) {
        mbar_wait(smem_u32 + (c % RSTG) * 8, (uint32_t)((c / RSTG) & 1));
        __syncthreads();   // readers of stage (c-1) done -> safe to refill (c+2)

        const int cn = c + RSTG - 1;
        if (cn < RNCH && tid == 0) {
            const uint32_t mb = smem_u32 + (cn % RSTG) * 8;
            const uint32_t dst = smem_u32 + TILE_BASE + (cn % RSTG) * STG_BYTES;
            mbar_expect_tx(mb, TX_BYTES);
            fence_async_shared();
            bulk_copy(dst,        srcA0 + (size_t)cn * 16384, 4096u, mb);
            bulk_copy(dst + 4096, srcA1 + (size_t)cn * 16384, 4096u, mb);
            #pragma unroll
            for (int j = 0; j < 8; j++) {
                bulk_copy(dst + 8192 + (j >> 2) * 8192 + (j & 3) * 2048,
                          srcB[j] + (size_t)cn * 131072, 2048u, mb);
            }
        }

        const uint32_t su = smem_u32 + TILE_BASE + (uint32_t)((c % RSTG) * STG_BYTES);
        #pragma unroll
        for (int ks = 0; ks < 4; ks++) {
            const uint32_t oa = (uint32_t)((wq * 16 + frow) * 128 + ks * 32 + fhalf);
            const uint32_t ob = (uint32_t)(frow * 128 + ks * 32 + fhalf);
            uint32_t ah[4]; uint32_t al[4]; uint32_t bh[4]; uint32_t bl[4];
            ldsm4(ah, su + swz128(oa));
            ldsm4(al, su + 4096u + swz128(oa));
            ldsm4(bh, su + 8192u + (uint32_t)(gp * 2048) + swz128(ob));
            ldsm4(bl, su + 16384u + (uint32_t)(gp * 2048) + swz128(ob));

            mma_bf16(acc0, ah, bh[0], bh[2]);
            mma_bf16(acc0, ah, bl[0], bl[2]);
            mma_bf16(acc0, al, bh[0], bh[2]);

            mma_bf16(acc1, ah, bh[1], bh[3]);
            mma_bf16(acc1, ah, bl[1], bl[3]);
            mma_bf16(acc1, al, bh[1], bh[3]);
        }
    }

    __syncthreads();
    // overlay fp32 staging on pipeline buffers: stage[gate][m 0..31][n 0..15]
    float* stage = (float*)(dynsm + TILE_BASE);
    {
        const int row  = lane >> 2;
        const int colp = (lane & 3) * 2;
        float* b0 = stage + (gp * RM + wq * 16 + row) * RN;
        float* b8 = stage + (gp * RM + wq * 16 + row + 8) * RN;
        b0[colp]     = acc0[0];
        b0[colp + 1] = acc0[1];
        b8[colp]     = acc0[2];
        b8[colp + 1] = acc0[3];
        b0[colp + 8] = acc1[0];
        b0[colp + 9] = acc1[1];
        b8[colp + 8] = acc1[2];
        b8[colp + 9] = acc1[3];
    }
    __syncthreads();

    // cell update: 32m x 16n = 512 cells, 2 consecutive n per thread
    {
        float2 pf = *(float2*)(stage + (0 * RM + erow) * RN + ecol2);
        float2 pi = *(float2*)(stage + (1 * RM + erow) * RN + ecol2);
        float2 pg = *(float2*)(stage + (2 * RM + erow) * RN + ecol2);
        float2 po = *(float2*)(stage + (3 * RM + erow) * RN + ecol2);

        float hv[2];
        float cn2[2];
        float pfv[2]; float piv[2]; float pgv[2]; float pov[2];
        float xfv[2]; float xiv[2]; float xgv[2]; float xov[2];
        float ccv[2];
        pfv[0]=pf.x; pfv[1]=pf.y;
        piv[0]=pi.x; piv[1]=pi.y;
        pgv[0]=pg.x; pgv[1]=pg.y;
        pov[0]=po.x; pov[1]=po.y;
        xfv[0]=xf.x; xfv[1]=xf.y;
        xiv[0]=xi.x; xiv[1]=xi.y;
        xgv[0]=xg.x; xgv[1]=xg.y;
        xov[0]=xo.x; xov[1]=xo.y;
        ccv[0]=cv.x; ccv[1]=cv.y;

        #pragma unroll
        for (int j = 0; j < 2; j++) {
            float fg = fast_sigmoid(pfv[j] + xfv[j]);
            float ig = fast_sigmoid(piv[j] + xiv[j]);
            float gg = fast_tanh(pgv[j] + xgv[j]);
            float og = fast_sigmoid(pov[j] + xov[j]);
            float c2 = fg * ccv[j] + ig * gg;
            cn2[j] = c2;
            hv[j] = og * fast_tanh(c2);
        }

        *(float2*)&g_c[(size_t)em * NH + en] = make_float2(cn2[0], cn2[1]);
        *(float2*)&g_h[(size_t)em * NH + en] = make_float2(hv[0], hv[1]);

        __nv_bfloat162 hh = __floats2bfloat162_rn(hv[0], hv[1]);
        float l0 = hv[0] - __bfloat162float(__low2bfloat16(hh));
        float l1 = hv[1] - __bfloat162float(__high2bfloat16(hh));
        // write next-step h in K-chunked pre-swizzled layout
        const uint32_t kc  = (uint32_t)(en >> 6);
        const uint32_t col = (uint32_t)(en & 63);
        const size_t byte = (size_t)kc * 16384u + swz128((uint32_t)em * 128u + col * 2u);
        *(__nv_bfloat162*)((char*)hout_hi + byte) = hh;
        *(__nv_bfloat162*)((char*)hout_lo + byte) = __floats2bfloat162_rn(l0, l1);
    }
}

// ---------------- bf16x3 input-projection GEMM (cp.async 3-stage, unchanged) --
__global__ __launch_bounds__(256) void proj_gemm(Ptr4 Bias)
{
    extern __shared__ __align__(16) unsigned char dynsm[];
    bf16* stg = (bf16*)dynsm;

    const int gate = blockIdx.z;
    const bf16* __restrict__ Bhi = g_Wx_hi + (size_t)gate * NH * NIN;
    const bf16* __restrict__ Blo = g_Wx_lo + (size_t)gate * NH * NIN;
    const float* __restrict__ bias = Bias.p[gate];

    const int tid   = threadIdx.x;
    const int warp  = tid >> 5;
    const int wm    = warp >> 2;
    const int wn    = warp & 3;
    const int mbase = blockIdx.y * BM;
    const int nbase = blockIdx.x * BN;

    const bf16* gsrc[4];
    int soff[4];
    #pragma unroll
    for (int l = 0; l < 4; l++) {
        int idx = l * 256 + tid;
        int p   = idx >> 8;
        int w   = idx & 255;
        int row = w >> 2;
        int q   = (w & 3) * 8;
        soff[l] = (p * BM + row) * SKS + q;
        if (p == 0) {
            gsrc[l] = g_x_hi + (size_t)(mbase + row) * NIN + q;
        } else if (p == 1) {
            gsrc[l] = g_x_lo + (size_t)(mbase + row) * NIN + q;
        } else if (p == 2) {
            gsrc[l] = Bhi + (size_t)(nbase + row) * NIN + q;
        } else {
            gsrc[l] = Blo + (size_t)(nbase + row) * NIN + q;
        }
    }

    wmma::fragment<wmma::accumulator, 16, 16, 16, float> acc0;
    wmma::fragment<wmma::accumulator, 16, 16, 16, float> acc1;
    wmma::fill_fragment(acc0, 0.0f);
    wmma::fill_fragment(acc1, 0.0f);

    const int NC = NIN / BK;   // 16

    #pragma unroll
    for (int s = 0; s < PSTAGES - 1; s++) {
        const int ko = s * BK;
        #pragma unroll
        for (int l = 0; l < 4; l++) {
            __pipeline_memcpy_async(stg + s * PSTB + soff[l], gsrc[l] + ko, 16);
        }
        __pipeline_commit();
    }

    for (int c = 0; c < NC; c++) {
        __pipeline_wait_prior(PSTAGES - 2);
        __syncthreads();

        const int cn = c + PSTAGES - 1;
        if (cn < NC) {
            const int ko = cn * BK;
            const int ds = cn % PSTAGES;
            #pragma unroll
            for (int l = 0; l < 4; l++) {
                __pipeline_memcpy_async(stg + ds * PSTB + soff[l], gsrc[l] + ko, 16);
            }
        }
        __pipeline_commit();

        bf16* sp = stg + (c % PSTAGES) * PSTB;
        #pragma unroll
        for (int ks = 0; ks < 2; ks++) {
            wmma::fragment<wmma::matrix_b, 16, 16, 16, bf16, wmma::col_major> fbh;
            wmma::fragment<wmma::matrix_b, 16, 16, 16, bf16, wmma::col_major> fbl;
            wmma::load_matrix_sync(fbh, sp + (2 * BM + wn * 16) * SKS + ks * 16, SKS);
            wmma::load_matrix_sync(fbl, sp + (3 * BM + wn * 16) * SKS + ks * 16, SKS);

            wmma::fragment<wmma::matrix_a, 16, 16, 16, bf16, wmma::row_major> fah;
            wmma::fragment<wmma::matrix_a, 16, 16, 16, bf16, wmma::row_major> fal;
            wmma::load_matrix_sync(fah, sp + (0 * BM + wm * 32) * SKS + ks * 16, SKS);
            wmma::load_matrix_sync(fal, sp + (1 * BM + wm * 32) * SKS + ks * 16, SKS);
            wmma::mma_sync(acc0, fah, fbh, acc0);
            wmma::mma_sync(acc0, fah, fbl, acc0);
            wmma::mma_sync(acc0, fal, fbh, acc0);

            wmma::load_matrix_sync(fah, sp + (0 * BM + wm * 32 + 16) * SKS + ks * 16, SKS);
            wmma::load_matrix_sync(fal, sp + (1 * BM + wm * 32 + 16) * SKS + ks * 16, SKS);
            wmma::mma_sync(acc1, fah, fbh, acc1);
            wmma::mma_sync(acc1, fah, fbl, acc1);
            wmma::mma_sync(acc1, fal, fbh, acc1);
        }
    }

    __pipeline_wait_prior(0);
    __syncthreads();
    float* stage = (float*)dynsm;   // 64 x 64 floats
    wmma::store_matrix_sync(stage + (wm * 32) * 64 + wn * 16, acc0, 64, wmma::mem_row_major);
    wmma::store_matrix_sync(stage + (wm * 32 + 16) * 64 + wn * 16, acc1, 64, wmma::mem_row_major);
    __syncthreads();

    #pragma unroll
    for (int i = 0; i < 4; i++) {
        int e   = tid + i * 256;
        int row = e >> 4;
        int c4  = (e & 15) * 4;
        int m   = mbase + row;
        int bb  = m >> 8;
        int ss  = m & 255;
        int col = nbase + c4;
        float4 v = *(float4*)(stage + row * 64 + c4);
        v.x += bias[col + 0];
        v.y += bias[col + 1];
        v.z += bias[col + 2];
        v.w += bias[col + 3];
        *(float4*)&g_xproj[(((size_t)gate * SEQ + ss) * BATCH + bb) * NH + col] = v;
    }
}

// ---------------- fp32 output GEMM (small) ----------------
__global__ __launch_bounds__(256) void out_gemm(const float* __restrict__ Wy,
                                                const float* __restrict__ by,
                                                float* __restrict__ out)
{
    __shared__ float As[TK][SROW];
    __shared__ float Bs[TK][SROW];
    const int tid = threadIdx.x;
    const int tx = tid & 15;
    const int ty = tid >> 4;
    const int mbase = blockIdx.y * TM;
    const int nbase = blockIdx.x * TN;
    const int lm = tid >> 2;
    const int lk = (tid & 3) << 2;

    float acc[4][4];
    #pragma unroll
    for (int i = 0; i < 4; i++) {
        #pragma unroll
        for (int j = 0; j < 4; j++) { acc[i][j] = 0.f; }
    }

    for (int kt = 0; kt < NH; kt += TK) {
        float4 av = *(const float4*)&g_h[(size_t)(mbase + lm) * NH + kt + lk];
        float4 bv = *(const float4*)&Wy [(size_t)(nbase + lm) * NH + kt + lk];
        __syncthreads();
        As[lk + 0][lm] = av.x; As[lk + 1][lm] = av.y;
        As[lk + 2][lm] = av.z; As[lk + 3][lm] = av.w;
        Bs[lk + 0][lm] = bv.x; Bs[lk + 1][lm] = bv.y;
        Bs[lk + 2][lm] = bv.z; Bs[lk + 3][lm] = bv.w;
        __syncthreads();
        #pragma unroll
        for (int k = 0; k < TK; k++) {
            float ar[4]; float br[4];
            #pragma unroll
            for (int i = 0; i < 4; i++) { ar[i] = As[k][(ty << 2) + i]; }
            #pragma unroll
            for (int j = 0; j < 4; j++) { br[j] = Bs[k][(tx << 2) + j]; }
            #pragma unroll
            for (int i = 0; i < 4; i++) {
                #pragma unroll
                for (int j = 0; j < 4; j++) { acc[i][j] = fmaf(ar[i], br[j], acc[i][j]); }
            }
        }
    }

    #pragma unroll
    for (int i = 0; i < 4; i++) {
        int m = mbase + (ty << 2) + i;
        int n0 = nbase + (tx << 2);
        #pragma unroll
        for (int j = 0; j < 4; j++) {
            out[(size_t)m * NOUT + n0 + j] = acc[i][j] + by[n0 + j];
        }
    }
}

__global__ __launch_bounds__(256) void copy_hc(float* __restrict__ out)
{
    const int idx = blockIdx.x * 256 + threadIdx.x;  // grid 512
    out[(size_t)BATCH * NOUT + idx]                      = g_h[idx];
    out[(size_t)BATCH * NOUT + (size_t)BATCH * NH + idx] = g_c[idx];
}

// ---------------------------------------------------------------------------
extern "C" void kernel_launch(void* const* d_in, const int* in_sizes, int n_in,
                              void* d_out, int out_size)
{
    const float* x_seq = (const float*)d_in[0];
    Ptr4 Wx; Ptr4 Bx; Ptr4 Wh;
    Wx.p[0] = (const float*)d_in[1];  Bx.p[0] = (const float*)d_in[2];  Wh.p[0] = (const float*)d_in[3];
    Wx.p[1] = (const float*)d_in[4];  Bx.p[1] = (const float*)d_in[5];  Wh.p[1] = (const float*)d_in[6];
    Wx.p[2] = (const float*)d_in[7];  Bx.p[2] = (const float*)d_in[8];  Wh.p[2] = (const float*)d_in[9];
    Wx.p[3] = (const float*)d_in[10]; Bx.p[3] = (const float*)d_in[11]; Wh.p[3] = (const float*)d_in[12];
    const float* Why_w = (const float*)d_in[13];
    const float* Why_b = (const float*)d_in[14];
    float* out = (float*)d_out;

    const int proj_smem = PSTAGES * PSTB * 2;   // 73728
    cudaFuncSetAttribute(rec_step,  cudaFuncAttributeMaxDynamicSharedMemorySize, REC_SMEM);
    cudaFuncSetAttribute(proj_gemm, cudaFuncAttributeMaxDynamicSharedMemorySize, proj_smem);

    fused_setup<<<65536, 256>>>(x_seq, Wh, Wx);

    proj_gemm<<<dim3(NH / BN, (BATCH * SEQ) / BM, 4), 256, proj_smem>>>(Bx);

    for (int t = 0; t < SEQ; t++) {
        rec_step<<<dim3(NH / RN, BATCH / RM), 256, REC_SMEM>>>(t);
    }

    out_gemm<<<dim3(NOUT / TN, BATCH / TM), 256>>>(Why_w, Why_b, out);
    copy_hc<<<512, 256>>>(out);
}

// round 14
// speedup vs baseline: 1.6253x; 1.0543x over previous
#include <cuda_runtime.h>
#include <cuda_bf16.h>
#include <mma.h>
#include <cuda_pipeline.h>

using namespace nvcuda;

#define BATCH 128
#define SEQ   256
#define NIN   512
#define NH    1024
#define NOUT  512

typedef __nv_bfloat16 bf16;

// proj GEMM tiling (unchanged, working)
#define BM 64
#define BN 64
#define BK 32
#define SKS 48
#define PSTAGES 3
#define PSTB (4 * BM * SKS)

// persistent rec: 128 blocks, block owns n-slice of 8 (x4 gates), all m, all K
#define RNB 8                    /* n per block */
#define RBLOCKS (NH / RNB)       /* 128 */
#define RKC 64
#define RNCH (NH / RKC)          /* 16 */
#define HOFF 1024                /* h stages base in smem */
#define HSTG 32768               /* one h stage: 2 planes x 16KB */
#define WOFF (HOFF + 2 * HSTG)   /* weights base = 66560 */
#define REC_SMEM (WOFF + 131072) /* 197632 */

// fp32 out_gemm tiling
#define TM 64
#define TN 64
#define TK 16
#define SROW 68

// ---------------- scratch (device globals) ----------------
__device__ float g_xproj[(size_t)4 * SEQ * BATCH * NH];
__device__ float g_h[BATCH * NH];
__device__ float g_c[BATCH * NH];
__device__ unsigned g_sync;
// h K-chunked SW128-pre-swizzled: [kc][m 0..127][64] (16KB per kc)
__device__ bf16  g_hA_hi[BATCH * NH];
__device__ bf16  g_hA_lo[BATCH * NH];
__device__ bf16  g_hB_hi[BATCH * NH];
__device__ bf16  g_hB_lo[BATCH * NH];
// Wh per-block layout: [b 0..127][kc 0..15][plane 0..1][32 rows x 128B swz]
__device__ bf16  g_Whr[(size_t)8 * NH * NH];
__device__ bf16  g_Wx_hi[(size_t)4 * NH * NIN];
__device__ bf16  g_Wx_lo[(size_t)4 * NH * NIN];
__device__ bf16  g_x_hi[(size_t)BATCH * SEQ * NIN];
__device__ bf16  g_x_lo[(size_t)BATCH * SEQ * NIN];

struct Ptr4 { const float* p[4]; };

__device__ __forceinline__ float fast_sigmoid(float x) { return 1.f / (1.f + __expf(-x)); }
__device__ __forceinline__ float fast_tanh(float x)    { return 2.f * fast_sigmoid(2.f * x) - 1.f; }
__device__ __forceinline__ uint32_t swz128(uint32_t o) { return o ^ ((o >> 3) & 0x70u); }

// ---------------- asm helpers ----------------
__device__ __forceinline__ void mbar_init(uint32_t a, uint32_t cnt)
{
    asm volatile("mbarrier.init.shared.b64 [ %0 ], %1;" :: "r"(a), "r"(cnt) : "memory");
}
__device__ __forceinline__ void mbar_expect_tx(uint32_t a, uint32_t bytes)
{
    asm volatile("mbarrier.arrive.expect_tx.shared.b64 _, [ %0 ], %1;"
                 :: "r"(a), "r"(bytes) : "memory");
}
__device__ __forceinline__ void mbar_wait(uint32_t a, uint32_t parity)
{
    asm volatile(
        "{ .reg .pred P1; "
        "LAB_%=: mbarrier.try_wait.parity.acquire.cta.shared::cta.b64 P1, [ %0 ], %1; "
        "@P1 bra DONE_%=; "
        "bra LAB_%=; "
        "DONE_%=: }"
        :: "r"(a), "r"(parity) : "memory");
}
__device__ __forceinline__ void bulk_copy(uint32_t dst, const void* src, uint32_t bytes,
                                          uint32_t mbar)
{
    asm volatile(
        "cp.async.bulk.shared::cluster.global.mbarrier::complete_tx::bytes "
        "[ %0 ], [ %1 ], %2, [ %3 ];"
        :: "r"(dst), "l"(src), "r"(bytes), "r"(mbar) : "memory");
}
__device__ __forceinline__ void fence_async_shared()
{
    asm volatile("fence.proxy.async.shared::cta;" ::: "memory");
}
__device__ __forceinline__ void ldsm4(uint32_t* r, uint32_t addr)
{
    asm volatile("ldmatrix.sync.aligned.m8n8.x4.shared.b16 { %0, %1, %2, %3 }, [ %4 ];"
                 : "=r"(r[0]), "=r"(r[1]), "=r"(r[2]), "=r"(r[3]) : "r"(addr));
}
__device__ __forceinline__ void mma_bf16(float* c, const uint32_t* a, uint32_t b0, uint32_t b1)
{
    asm volatile(
        "mma.sync.aligned.m16n8k16.row.col.f32.bf16.bf16.f32 "
        "{ %0, %1, %2, %3 }, { %4, %5, %6, %7 }, { %8, %9 }, { %0, %1, %2, %3 };"
        : "+f"(c[0]), "+f"(c[1]), "+f"(c[2]), "+f"(c[3])
        : "r"(a[0]), "r"(a[1]), "r"(a[2]), "r"(a[3]), "r"(b0), "r"(b1));
}

// ---------------- fused setup ----------------
__global__ __launch_bounds__(256) void fused_setup(const float* __restrict__ x,
                                                   Ptr4 Wh, Ptr4 Wx)
{
    const size_t idx = (size_t)blockIdx.x * 256 + threadIdx.x;
    if (idx == 0) { g_sync = 0u; }
    {
        float v = x[idx];
        bf16 hv = __float2bfloat16_rn(v);
        g_x_hi[idx] = hv;
        g_x_lo[idx] = __float2bfloat16_rn(v - __bfloat162float(hv));
    }
    if (idx < (size_t)4 * NH * NH) {
        int gate = (int)(idx >> 20);
        uint32_t r = (uint32_t)(idx & ((1u << 20) - 1));
        float v = Wh.p[gate][r];
        bf16 hv = __float2bfloat16_rn(v);
        bf16 lv = __float2bfloat16_rn(v - __bfloat162float(hv));
        uint32_t n = r >> 10;
        uint32_t k = r & 1023u;
        uint32_t b = n >> 3;
        uint32_t row32 = (uint32_t)gate * 8u + (n & 7u);
        uint32_t kc = k >> 6;
        uint32_t col = k & 63u;
        size_t base = (size_t)b * 131072u + (size_t)kc * 8192u;
        uint32_t sw = swz128(row32 * 128u + col * 2u);
        *(bf16*)((char*)g_Whr + base + sw) = hv;              // plane 0 (hi)
        *(bf16*)((char*)g_Whr + base + 4096u + sw) = lv;      // plane 1 (lo)
    }
    if (idx < (size_t)4 * NH * NIN) {
        int gate = (int)(idx >> 19);
        float v = Wx.p[gate][idx & ((1u << 19) - 1)];
        bf16 hv = __float2bfloat16_rn(v);
        g_Wx_hi[idx] = hv;
        g_Wx_lo[idx] = __float2bfloat16_rn(v - __bfloat162float(hv));
    }
    if (idx < (size_t)BATCH * NH) {
        g_h[idx] = 0.f;
        g_c[idx] = 0.f;
        g_hA_hi[idx] = __float2bfloat16_rn(0.f);
        g_hA_lo[idx] = __float2bfloat16_rn(0.f);
    }
}

// ---------------- persistent weight-stationary recurrence ----------------
// grid 128 blocks (all resident), 256 threads (8 warps). Block b owns
// n in [b*8, b*8+8) for ALL 4 gates, all 128 m, all K. Weights live in smem.
// Warp w: m rows [w*16, w*16+16), all 32 output cols (acc[g] = gate g, 16m x 8n).
__global__ __launch_bounds__(256) void rec_persistent()
{
    extern __shared__ __align__(128) unsigned char dynsm[];
    const uint32_t smem_u32 = (uint32_t)__cvta_generic_to_shared(dynsm);

    const int tid  = threadIdx.x;
    const int w    = tid >> 5;
    const int lane = tid & 31;
    const int nbase = blockIdx.x * RNB;

    if (tid == 0) {
        mbar_init(smem_u32 + 0, 1);
        mbar_init(smem_u32 + 8, 1);
        mbar_init(smem_u32 + 16, 1);
        fence_async_shared();
    }
    __syncthreads();

    // one-time weight load: 16 copies of 8KB into WOFF
    if (tid == 0) {
        mbar_expect_tx(smem_u32 + 16, 131072u);
        const char* wsrc = (const char*)g_Whr + (size_t)blockIdx.x * 131072u;
        #pragma unroll
        for (int kc = 0; kc < 16; kc++) {
            bulk_copy(smem_u32 + WOFF + kc * 8192, wsrc + (size_t)kc * 8192, 8192u,
                      smem_u32 + 16);
        }
    }
    mbar_wait(smem_u32 + 16, 0u);

    const int frow  = lane & 15;
    const int fhalf = (lane >> 4) << 4;
    const int m0   = w * 16 + (lane >> 2);   // +8 for half 1
    const int en0  = nbase + (lane & 3) * 2;
    const size_t BH = (size_t)BATCH * NH;
    const uint32_t kc_h  = (uint32_t)(en0 >> 6);
    const uint32_t col_h = (uint32_t)(en0 & 63);

    float creg[4];
    #pragma unroll
    for (int q = 0; q < 4; q++) { creg[q] = 0.f; }

    for (int t = 0; t < SEQ; t++) {
        const int par = t & 1;
        const char* hin_hi = (const char*)(par ? g_hB_hi : g_hA_hi);
        const char* hin_lo = (const char*)(par ? g_hB_lo : g_hA_lo);
        bf16* hout_hi = par ? g_hA_hi : g_hB_hi;
        bf16* hout_lo = par ? g_hA_lo : g_hB_lo;

        // xproj prefetch for this thread's 4 cells x 4 gates
        float xp[4][4];
        #pragma unroll
        for (int g = 0; g < 4; g++) {
            #pragma unroll
            for (int half = 0; half < 2; half++) {
                const int em = m0 + half * 8;
                float2 v = *(const float2*)&g_xproj[((size_t)(g * SEQ) + t) * BH
                                                    + (size_t)em * NH + en0];
                xp[g][half * 2]     = v.x;
                xp[g][half * 2 + 1] = v.y;
            }
        }

        // prologue: chunk 0 into stage 0
        if (tid == 0) {
            fence_async_shared();
            mbar_expect_tx(smem_u32 + 0, 32768u);
            bulk_copy(smem_u32 + HOFF,         hin_hi, 16384u, smem_u32 + 0);
            bulk_copy(smem_u32 + HOFF + 16384, hin_lo, 16384u, smem_u32 + 0);
        }

        float acc[4][4];
        #pragma unroll
        for (int g = 0; g < 4; g++) {
            #pragma unroll
            for (int q = 0; q < 4; q++) { acc[g][q] = 0.f; }
        }

        for (int c = 0; c < RNCH; c++) {
            const int st = c & 1;
            const uint32_t parity = (uint32_t)((t * 8 + (c >> 1)) & 1);
            mbar_wait(smem_u32 + st * 8, parity);
            __syncthreads();

            const int cn = c + 1;
            if (cn < RNCH && tid == 0) {
                const int stn = cn & 1;
                fence_async_shared();
                mbar_expect_tx(smem_u32 + stn * 8, 32768u);
                bulk_copy(smem_u32 + HOFF + stn * HSTG,
                          hin_hi + (size_t)cn * 16384, 16384u, smem_u32 + stn * 8);
                bulk_copy(smem_u32 + HOFF + stn * HSTG + 16384,
                          hin_lo + (size_t)cn * 16384, 16384u, smem_u32 + stn * 8);
            }

            const uint32_t abase = smem_u32 + HOFF + (uint32_t)(st * HSTG);
            const uint32_t wbase = smem_u32 + WOFF + (uint32_t)(c * 8192);
            #pragma unroll
            for (int ks = 0; ks < 4; ks++) {
                const uint32_t oa  = (uint32_t)((w * 16 + frow) * 128 + ks * 32 + fhalf);
                const uint32_t ob0 = (uint32_t)(frow * 128 + ks * 32 + fhalf);
                const uint32_t ob1 = (uint32_t)((16 + frow) * 128 + ks * 32 + fhalf);
                uint32_t ah[4]; uint32_t al[4];
                uint32_t bh0[4]; uint32_t bh1[4]; uint32_t bl0[4]; uint32_t bl1[4];
                ldsm4(ah, abase + swz128(oa));
                ldsm4(al, abase + 16384u + swz128(oa));
                ldsm4(bh0, wbase + swz128(ob0));
                ldsm4(bh1, wbase + swz128(ob1));
                ldsm4(bl0, wbase + 4096u + swz128(ob0));
                ldsm4(bl1, wbase + 4096u + swz128(ob1));

                mma_bf16(acc[0], ah, bh0[0], bh0[2]);
                mma_bf16(acc[0], ah, bl0[0], bl0[2]);
                mma_bf16(acc[0], al, bh0[0], bh0[2]);

                mma_bf16(acc[1], ah, bh0[1], bh0[3]);
                mma_bf16(acc[1], ah, bl0[1], bl0[3]);
                mma_bf16(acc[1], al, bh0[1], bh0[3]);

                mma_bf16(acc[2], ah, bh1[0], bh1[2]);
                mma_bf16(acc[2], ah, bl1[0], bl1[2]);
                mma_bf16(acc[2], al, bh1[0], bh1[2]);

                mma_bf16(acc[3], ah, bh1[1], bh1[3]);
                mma_bf16(acc[3], ah, bl1[1], bl1[3]);
                mma_bf16(acc[3], al, bh1[1], bh1[3]);
            }
        }

        // epilogue: pure-register cell update (2 m-rows x 2 n per thread)
        #pragma unroll
        for (int half = 0; half < 2; half++) {
            const int em = m0 + half * 8;
            float hv[2];
            #pragma unroll
            for (int j = 0; j < 2; j++) {
                const int q = half * 2 + j;
                float fg = fast_sigmoid(acc[0][q] + xp[0][q]);
                float ig = fast_sigmoid(acc[1][q] + xp[1][q]);
                float gg = fast_tanh(acc[2][q] + xp[2][q]);
                float og = fast_sigmoid(acc[3][q] + xp[3][q]);
                float c2 = fg * creg[q] + ig * gg;
                creg[q] = c2;
                hv[j] = og * fast_tanh(c2);
            }
            *(float2*)&g_h[(size_t)em * NH + en0] = make_float2(hv[0], hv[1]);

            __nv_bfloat162 hh = __floats2bfloat162_rn(hv[0], hv[1]);
            float l0 = hv[0] - __bfloat162float(__low2bfloat16(hh));
            float l1 = hv[1] - __bfloat162float(__high2bfloat16(hh));
            const size_t byte = (size_t)kc_h * 16384u
                              + swz128((uint32_t)em * 128u + col_h * 2u);
            *(__nv_bfloat162*)((char*)hout_hi + byte) = hh;
            *(__nv_bfloat162*)((char*)hout_lo + byte) = __floats2bfloat162_rn(l0, l1);
        }

        // grid barrier (all 128 blocks resident)
        if (t < SEQ - 1) {
            __threadfence();
            __syncthreads();
            if (tid == 0) {
                atomicAdd(&g_sync, 1u);
                const unsigned target = (unsigned)(RBLOCKS * (t + 1));
                while (*((volatile unsigned*)&g_sync) < target) { }
            }
            __syncthreads();
        }
    }

    // final c
    #pragma unroll
    for (int half = 0; half < 2; half++) {
        const int em = m0 + half * 8;
        *(float2*)&g_c[(size_t)em * NH + en0] = make_float2(creg[half * 2], creg[half * 2 + 1]);
    }
}

// ---------------- bf16x3 input-projection GEMM (cp.async 3-stage, unchanged) --
__global__ __launch_bounds__(256) void proj_gemm(Ptr4 Bias)
{
    extern __shared__ __align__(16) unsigned char dynsm[];
    bf16* stg = (bf16*)dynsm;

    const int gate = blockIdx.z;
    const bf16* __restrict__ Bhi = g_Wx_hi + (size_t)gate * NH * NIN;
    const bf16* __restrict__ Blo = g_Wx_lo + (size_t)gate * NH * NIN;
    const float* __restrict__ bias = Bias.p[gate];

    const int tid   = threadIdx.x;
    const int warp  = tid >> 5;
    const int wm    = warp >> 2;
    const int wn    = warp & 3;
    const int mbase = blockIdx.y * BM;
    const int nbase = blockIdx.x * BN;

    const bf16* gsrc[4];
    int soff[4];
    #pragma unroll
    for (int l = 0; l < 4; l++) {
        int idx = l * 256 + tid;
        int p   = idx >> 8;
        int w2  = idx & 255;
        int row = w2 >> 2;
        int q   = (w2 & 3) * 8;
        soff[l] = (p * BM + row) * SKS + q;
        if (p == 0) {
            gsrc[l] = g_x_hi + (size_t)(mbase + row) * NIN + q;
        } else if (p == 1) {
            gsrc[l] = g_x_lo + (size_t)(mbase + row) * NIN + q;
        } else if (p == 2) {
            gsrc[l] = Bhi + (size_t)(nbase + row) * NIN + q;
        } else {
            gsrc[l] = Blo + (size_t)(nbase + row) * NIN + q;
        }
    }

    wmma::fragment<wmma::accumulator, 16, 16, 16, float> acc0;
    wmma::fragment<wmma::accumulator, 16, 16, 16, float> acc1;
    wmma::fill_fragment(acc0, 0.0f);
    wmma::fill_fragment(acc1, 0.0f);

    const int NC = NIN / BK;   // 16

    #pragma unroll
    for (int s = 0; s < PSTAGES - 1; s++) {
        const int ko = s * BK;
        #pragma unroll
        for (int l = 0; l < 4; l++) {
            __pipeline_memcpy_async(stg + s * PSTB + soff[l], gsrc[l] + ko, 16);
        }
        __pipeline_commit();
    }

    for (int c = 0; c < NC; c++) {
        __pipeline_wait_prior(PSTAGES - 2);
        __syncthreads();

        const int cn = c + PSTAGES - 1;
        if (cn < NC) {
            const int ko = cn * BK;
            const int ds = cn % PSTAGES;
            #pragma unroll
            for (int l = 0; l < 4; l++) {
                __pipeline_memcpy_async(stg + ds * PSTB + soff[l], gsrc[l] + ko, 16);
            }
        }
        __pipeline_commit();

        bf16* sp = stg + (c % PSTAGES) * PSTB;
        #pragma unroll
        for (int ks = 0; ks < 2; ks++) {
            wmma::fragment<wmma::matrix_b, 16, 16, 16, bf16, wmma::col_major> fbh;
            wmma::fragment<wmma::matrix_b, 16, 16, 16, bf16, wmma::col_major> fbl;
            wmma::load_matrix_sync(fbh, sp + (2 * BM + wn * 16) * SKS + ks * 16, SKS);
            wmma::load_matrix_sync(fbl, sp + (3 * BM + wn * 16) * SKS + ks * 16, SKS);

            wmma::fragment<wmma::matrix_a, 16, 16, 16, bf16, wmma::row_major> fah;
            wmma::fragment<wmma::matrix_a, 16, 16, 16, bf16, wmma::row_major> fal;
            wmma::load_matrix_sync(fah, sp + (0 * BM + wm * 32) * SKS + ks * 16, SKS);
            wmma::load_matrix_sync(fal, sp + (1 * BM + wm * 32) * SKS + ks * 16, SKS);
            wmma::mma_sync(acc0, fah, fbh, acc0);
            wmma::mma_sync(acc0, fah, fbl, acc0);
            wmma::mma_sync(acc0, fal, fbh, acc0);

            wmma::load_matrix_sync(fah, sp + (0 * BM + wm * 32 + 16) * SKS + ks * 16, SKS);
            wmma::load_matrix_sync(fal, sp + (1 * BM + wm * 32 + 16) * SKS + ks * 16, SKS);
            wmma::mma_sync(acc1, fah, fbh, acc1);
            wmma::mma_sync(acc1, fah, fbl, acc1);
            wmma::mma_sync(acc1, fal, fbh, acc1);
        }
    }

    __pipeline_wait_prior(0);
    __syncthreads();
    float* stage = (float*)dynsm;   // 64 x 64 floats
    wmma::store_matrix_sync(stage + (wm * 32) * 64 + wn * 16, acc0, 64, wmma::mem_row_major);
    wmma::store_matrix_sync(stage + (wm * 32 + 16) * 64 + wn * 16, acc1, 64, wmma::mem_row_major);
    __syncthreads();

    #pragma unroll
    for (int i = 0; i < 4; i++) {
        int e   = tid + i * 256;
        int row = e >> 4;
        int c4  = (e & 15) * 4;
        int m   = mbase + row;
        int bb  = m >> 8;
        int ss  = m & 255;
        int col = nbase + c4;
        float4 v = *(float4*)(stage + row * 64 + c4);
        v.x += bias[col + 0];
        v.y += bias[col + 1];
        v.z += bias[col + 2];
        v.w += bias[col + 3];
        *(float4*)&g_xproj[(((size_t)gate * SEQ + ss) * BATCH + bb) * NH + col] = v;
    }
}

// ---------------- fp32 output GEMM (small) ----------------
__global__ __launch_bounds__(256) void out_gemm(const float* __restrict__ Wy,
                                                const float* __restrict__ by,
                                                float* __restrict__ out)
{
    __shared__ float As[TK][SROW];
    __shared__ float Bs[TK][SROW];
    const int tid = threadIdx.x;
    const int tx = tid & 15;
    const int ty = tid >> 4;
    const int mbase = blockIdx.y * TM;
    const int nbase = blockIdx.x * TN;
    const int lm = tid >> 2;
    const int lk = (tid & 3) << 2;

    float acc[4][4];
    #pragma unroll
    for (int i = 0; i < 4; i++) {
        #pragma unroll
        for (int j = 0; j < 4; j++) { acc[i][j] = 0.f; }
    }

    for (int kt = 0; kt < NH; kt += TK) {
        float4 av = *(const float4*)&g_h[(size_t)(mbase + lm) * NH + kt + lk];
        float4 bv = *(const float4*)&Wy [(size_t)(nbase + lm) * NH + kt + lk];
        __syncthreads();
        As[lk + 0][lm] = av.x; As[lk + 1][lm] = av.y;
        As[lk + 2][lm] = av.z; As[lk + 3][lm] = av.w;
        Bs[lk + 0][lm] = bv.x; Bs[lk + 1][lm] = bv.y;
        Bs[lk + 2][lm] = bv.z; Bs[lk + 3][lm] = bv.w;
        __syncthreads();
        #pragma unroll
        for (int k = 0; k < TK; k++) {
            float ar[4]; float br[4];
            #pragma unroll
            for (int i = 0; i < 4; i++) { ar[i] = As[k][(ty << 2) + i]; }
            #pragma unroll
            for (int j = 0; j < 4; j++) { br[j] = Bs[k][(tx << 2) + j]; }
            #pragma unroll
            for (int i = 0; i < 4; i++) {
                #pragma unroll
                for (int j = 0; j < 4; j++) { acc[i][j] = fmaf(ar[i], br[j], acc[i][j]); }
            }
        }
    }

    #pragma unroll
    for (int i = 0; i < 4; i++) {
        int m = mbase + (ty << 2) + i;
        int n0 = nbase + (tx << 2);
        #pragma unroll
        for (int j = 0; j < 4; j++) {
            out[(size_t)m * NOUT + n0 + j] = acc[i][j] + by[n0 + j];
        }
    }
}

__global__ __launch_bounds__(256) void copy_hc(float* __restrict__ out)
{
    const int idx = blockIdx.x * 256 + threadIdx.x;  // grid 512
    out[(size_t)BATCH * NOUT + idx]                      = g_h[idx];
    out[(size_t)BATCH * NOUT + (size_t)BATCH * NH + idx] = g_c[idx];
}

// ---------------------------------------------------------------------------
extern "C" void kernel_launch(void* const* d_in, const int* in_sizes, int n_in,
                              void* d_out, int out_size)
{
    const float* x_seq = (const float*)d_in[0];
    Ptr4 Wx; Ptr4 Bx; Ptr4 Wh;
    Wx.p[0] = (const float*)d_in[1];  Bx.p[0] = (const float*)d_in[2];  Wh.p[0] = (const float*)d_in[3];
    Wx.p[1] = (const float*)d_in[4];  Bx.p[1] = (const float*)d_in[5];  Wh.p[1] = (const float*)d_in[6];
    Wx.p[2] = (const float*)d_in[7];  Bx.p[2] = (const float*)d_in[8];  Wh.p[2] = (const float*)d_in[9];
    Wx.p[3] = (const float*)d_in[10]; Bx.p[3] = (const float*)d_in[11]; Wh.p[3] = (const float*)d_in[12];
    const float* Why_w = (const float*)d_in[13];
    const float* Why_b = (const float*)d_in[14];
    float* out = (float*)d_out;

    const int proj_smem = PSTAGES * PSTB * 2;   // 73728
    cudaFuncSetAttribute(rec_persistent, cudaFuncAttributeMaxDynamicSharedMemorySize, REC_SMEM);
    cudaFuncSetAttribute(proj_gemm, cudaFuncAttributeMaxDynamicSharedMemorySize, proj_smem);

    fused_setup<<<65536, 256>>>(x_seq, Wh, Wx);

    proj_gemm<<<dim3(NH / BN, (BATCH * SEQ) / BM, 4), 256, proj_smem>>>(Bx);

    rec_persistent<<<RBLOCKS, 256, REC_SMEM>>>();

    out_gemm<<<dim3(NOUT / TN, BATCH / TM), 256>>>(Why_w, Why_b, out);
    copy_hc<<<512, 256>>>(out);
}

// round 15
// speedup vs baseline: 1.8519x; 1.1395x over previous
#include <cuda_runtime.h>
#include <cuda_bf16.h>
#include <cuda_pipeline.h>

#define BATCH 128
#define SEQ   256
#define NIN   512
#define NH    1024
#define NOUT  512

typedef __nv_bfloat16 bf16;

// persistent rec: 128 blocks, block owns n-slice of 8 (x4 gates), all m, all K
#define RNB 8
#define RBLOCKS (NH / RNB)       /* 128 */
#define RKC 64
#define RNCH (NH / RKC)          /* 16 */
#define HOFF 1024
#define HSTG 32768
#define WOFF (HOFF + 2 * HSTG)
#define REC_SMEM (WOFF + 131072) /* 197632 */

// proj v2: 128m x 128n tiles, K-chunk 64, bulk-copy fed
#define PKC 8                    /* 512 / 64 */
#define PSTG 65536               /* A hi/lo 16KB + B hi/lo 16KB */
#define PROJ_SMEM (1024 + 2 * PSTG)   /* 132096 */

// fp32 out_gemm tiling
#define TM 64
#define TN 64
#define TK 16
#define SROW 68

// ---------------- scratch (device globals) ----------------
__device__ float g_xproj[(size_t)4 * SEQ * BATCH * NH];
__device__ float g_h[BATCH * NH];
__device__ float g_c[BATCH * NH];
__device__ unsigned g_sync;
// h K-chunked SW128-pre-swizzled: [kc][m 0..127][64] (16KB per kc)
__device__ bf16  g_hA_hi[BATCH * NH];
__device__ bf16  g_hA_lo[BATCH * NH];
__device__ bf16  g_hB_hi[BATCH * NH];
__device__ bf16  g_hB_lo[BATCH * NH];
// Wh per-block layout: [b 0..127][kc 0..15][plane 0..1][32 rows x 128B swz]
__device__ bf16  g_Whr[(size_t)8 * NH * NH];
// x K-chunked SW128-pre-swizzled: [kc 0..7][m 0..32767][64]
__device__ bf16  g_xr_hi[(size_t)BATCH * SEQ * NIN];
__device__ bf16  g_xr_lo[(size_t)BATCH * SEQ * NIN];
// Wx K-chunked SW128-pre-swizzled: [gate][kc 0..7][n 0..1023][64]
__device__ bf16  g_Wxr_hi[(size_t)4 * NH * NIN];
__device__ bf16  g_Wxr_lo[(size_t)4 * NH * NIN];

struct Ptr4 { const float* p[4]; };

__device__ __forceinline__ float fast_sigmoid(float x) { return 1.f / (1.f + __expf(-x)); }
__device__ __forceinline__ float fast_tanh(float x)    { return 2.f * fast_sigmoid(2.f * x) - 1.f; }
__device__ __forceinline__ uint32_t swz128(uint32_t o) { return o ^ ((o >> 3) & 0x70u); }

// ---------------- asm helpers ----------------
__device__ __forceinline__ void mbar_init(uint32_t a, uint32_t cnt)
{
    asm volatile("mbarrier.init.shared.b64 [ %0 ], %1;" :: "r"(a), "r"(cnt) : "memory");
}
__device__ __forceinline__ void mbar_expect_tx(uint32_t a, uint32_t bytes)
{
    asm volatile("mbarrier.arrive.expect_tx.shared.b64 _, [ %0 ], %1;"
                 :: "r"(a), "r"(bytes) : "memory");
}
__device__ __forceinline__ void mbar_wait(uint32_t a, uint32_t parity)
{
    asm volatile(
        "{ .reg .pred P1; "
        "LAB_%=: mbarrier.try_wait.parity.acquire.cta.shared::cta.b64 P1, [ %0 ], %1; "
        "@P1 bra DONE_%=; "
        "bra LAB_%=; "
        "DONE_%=: }"
        :: "r"(a), "r"(parity) : "memory");
}
__device__ __forceinline__ void bulk_copy(uint32_t dst, const void* src, uint32_t bytes,
                                          uint32_t mbar)
{
    asm volatile(
        "cp.async.bulk.shared::cluster.global.mbarrier::complete_tx::bytes "
        "[ %0 ], [ %1 ], %2, [ %3 ];"
        :: "r"(dst), "l"(src), "r"(bytes), "r"(mbar) : "memory");
}
__device__ __forceinline__ void fence_async_shared()
{
    asm volatile("fence.proxy.async.shared::cta;" ::: "memory");
}
__device__ __forceinline__ void ldsm4(uint32_t* r, uint32_t addr)
{
    asm volatile("ldmatrix.sync.aligned.m8n8.x4.shared.b16 { %0, %1, %2, %3 }, [ %4 ];"
                 : "=r"(r[0]), "=r"(r[1]), "=r"(r[2]), "=r"(r[3]) : "r"(addr));
}
__device__ __forceinline__ void mma_bf16(float* c, const uint32_t* a, uint32_t b0, uint32_t b1)
{
    asm volatile(
        "mma.sync.aligned.m16n8k16.row.col.f32.bf16.bf16.f32 "
        "{ %0, %1, %2, %3 }, { %4, %5, %6, %7 }, { %8, %9 }, { %0, %1, %2, %3 };"
        : "+f"(c[0]), "+f"(c[1]), "+f"(c[2]), "+f"(c[3])
        : "r"(a[0]), "r"(a[1]), "r"(a[2]), "r"(a[3]), "r"(b0), "r"(b1));
}

// ---------------- fused setup ----------------
__global__ __launch_bounds__(256) void fused_setup(const float* __restrict__ x,
                                                   Ptr4 Wh, Ptr4 Wx)
{
    const size_t idx = (size_t)blockIdx.x * 256 + threadIdx.x;
    if (idx == 0) { g_sync = 0u; }
    {
        // x -> K-chunked swizzled planes
        float v = x[idx];
        bf16 hv = __float2bfloat16_rn(v);
        bf16 lv = __float2bfloat16_rn(v - __bfloat162float(hv));
        uint32_t m = (uint32_t)(idx >> 9);
        uint32_t k = (uint32_t)(idx & 511u);
        size_t byte = (size_t)(k >> 6) * 4194304u + swz128(m * 128u + (k & 63u) * 2u);
        *(bf16*)((char*)g_xr_hi + byte) = hv;
        *(bf16*)((char*)g_xr_lo + byte) = lv;
    }
    if (idx < (size_t)4 * NH * NH) {
        int gate = (int)(idx >> 20);
        uint32_t r = (uint32_t)(idx & ((1u << 20) - 1));
        float v = Wh.p[gate][r];
        bf16 hv = __float2bfloat16_rn(v);
        bf16 lv = __float2bfloat16_rn(v - __bfloat162float(hv));
        uint32_t n = r >> 10;
        uint32_t k = r & 1023u;
        uint32_t b = n >> 3;
        uint32_t row32 = (uint32_t)gate * 8u + (n & 7u);
        size_t base = (size_t)b * 131072u + (size_t)(k >> 6) * 8192u;
        uint32_t sw = swz128(row32 * 128u + (k & 63u) * 2u);
        *(bf16*)((char*)g_Whr + base + sw) = hv;
        *(bf16*)((char*)g_Whr + base + 4096u + sw) = lv;
    }
    if (idx < (size_t)4 * NH * NIN) {
        int gate = (int)(idx >> 19);
        uint32_t r = (uint32_t)(idx & ((1u << 19) - 1));
        float v = Wx.p[gate][r];
        bf16 hv = __float2bfloat16_rn(v);
        bf16 lv = __float2bfloat16_rn(v - __bfloat162float(hv));
        uint32_t n = r >> 9;
        uint32_t k = r & 511u;
        size_t byte = (size_t)gate * 1048576u + (size_t)(k >> 6) * 131072u
                    + swz128(n * 128u + (k & 63u) * 2u);
        *(bf16*)((char*)g_Wxr_hi + byte) = hv;
        *(bf16*)((char*)g_Wxr_lo + byte) = lv;
    }
    if (idx < (size_t)BATCH * NH) {
        g_h[idx] = 0.f;
        g_c[idx] = 0.f;
        g_hA_hi[idx] = __float2bfloat16_rn(0.f);
        g_hA_lo[idx] = __float2bfloat16_rn(0.f);
    }
}

// ---------------- persistent weight-stationary recurrence (unchanged R14) ----
__global__ __launch_bounds__(256) void rec_persistent()
{
    extern __shared__ __align__(128) unsigned char dynsm[];
    const uint32_t smem_u32 = (uint32_t)__cvta_generic_to_shared(dynsm);

    const int tid  = threadIdx.x;
    const int w    = tid >> 5;
    const int lane = tid & 31;
    const int nbase = blockIdx.x * RNB;

    if (tid == 0) {
        mbar_init(smem_u32 + 0, 1);
        mbar_init(smem_u32 + 8, 1);
        mbar_init(smem_u32 + 16, 1);
        fence_async_shared();
    }
    __syncthreads();

    if (tid == 0) {
        mbar_expect_tx(smem_u32 + 16, 131072u);
        const char* wsrc = (const char*)g_Whr + (size_t)blockIdx.x * 131072u;
        #pragma unroll
        for (int kc = 0; kc < 16; kc++) {
            bulk_copy(smem_u32 + WOFF + kc * 8192, wsrc + (size_t)kc * 8192, 8192u,
                      smem_u32 + 16);
        }
    }
    mbar_wait(smem_u32 + 16, 0u);

    const int frow  = lane & 15;
    const int fhalf = (lane >> 4) << 4;
    const int m0   = w * 16 + (lane >> 2);
    const int en0  = nbase + (lane & 3) * 2;
    const size_t BH = (size_t)BATCH * NH;
    const uint32_t kc_h  = (uint32_t)(en0 >> 6);
    const uint32_t col_h = (uint32_t)(en0 & 63);

    float creg[4];
    #pragma unroll
    for (int q = 0; q < 4; q++) { creg[q] = 0.f; }

    for (int t = 0; t < SEQ; t++) {
        const int par = t & 1;
        const char* hin_hi = (const char*)(par ? g_hB_hi : g_hA_hi);
        const char* hin_lo = (const char*)(par ? g_hB_lo : g_hA_lo);
        bf16* hout_hi = par ? g_hA_hi : g_hB_hi;
        bf16* hout_lo = par ? g_hA_lo : g_hB_lo;

        float xp[4][4];
        #pragma unroll
        for (int g = 0; g < 4; g++) {
            #pragma unroll
            for (int half = 0; half < 2; half++) {
                const int em = m0 + half * 8;
                float2 v = *(const float2*)&g_xproj[((size_t)(g * SEQ) + t) * BH
                                                    + (size_t)em * NH + en0];
                xp[g][half * 2]     = v.x;
                xp[g][half * 2 + 1] = v.y;
            }
        }

        if (tid == 0) {
            fence_async_shared();
            mbar_expect_tx(smem_u32 + 0, 32768u);
            bulk_copy(smem_u32 + HOFF,         hin_hi, 16384u, smem_u32 + 0);
            bulk_copy(smem_u32 + HOFF + 16384, hin_lo, 16384u, smem_u32 + 0);
        }

        float acc[4][4];
        #pragma unroll
        for (int g = 0; g < 4; g++) {
            #pragma unroll
            for (int q = 0; q < 4; q++) { acc[g][q] = 0.f; }
        }

        for (int c = 0; c < RNCH; c++) {
            const int st = c & 1;
            const uint32_t parity = (uint32_t)((t * 8 + (c >> 1)) & 1);
            mbar_wait(smem_u32 + st * 8, parity);
            __syncthreads();

            const int cn = c + 1;
            if (cn < RNCH && tid == 0) {
                const int stn = cn & 1;
                fence_async_shared();
                mbar_expect_tx(smem_u32 + stn * 8, 32768u);
                bulk_copy(smem_u32 + HOFF + stn * HSTG,
                          hin_hi + (size_t)cn * 16384, 16384u, smem_u32 + stn * 8);
                bulk_copy(smem_u32 + HOFF + stn * HSTG + 16384,
                          hin_lo + (size_t)cn * 16384, 16384u, smem_u32 + stn * 8);
            }

            const uint32_t abase = smem_u32 + HOFF + (uint32_t)(st * HSTG);
            const uint32_t wbase = smem_u32 + WOFF + (uint32_t)(c * 8192);
            #pragma unroll
            for (int ks = 0; ks < 4; ks++) {
                const uint32_t oa  = (uint32_t)((w * 16 + frow) * 128 + ks * 32 + fhalf);
                const uint32_t ob0 = (uint32_t)(frow * 128 + ks * 32 + fhalf);
                const uint32_t ob1 = (uint32_t)((16 + frow) * 128 + ks * 32 + fhalf);
                uint32_t ah[4]; uint32_t al[4];
                uint32_t bh0[4]; uint32_t bh1[4]; uint32_t bl0[4]; uint32_t bl1[4];
                ldsm4(ah, abase + swz128(oa));
                ldsm4(al, abase + 16384u + swz128(oa));
                ldsm4(bh0, wbase + swz128(ob0));
                ldsm4(bh1, wbase + swz128(ob1));
                ldsm4(bl0, wbase + 4096u + swz128(ob0));
                ldsm4(bl1, wbase + 4096u + swz128(ob1));

                mma_bf16(acc[0], ah, bh0[0], bh0[2]);
                mma_bf16(acc[0], ah, bl0[0], bl0[2]);
                mma_bf16(acc[0], al, bh0[0], bh0[2]);

                mma_bf16(acc[1], ah, bh0[1], bh0[3]);
                mma_bf16(acc[1], ah, bl0[1], bl0[3]);
                mma_bf16(acc[1], al, bh0[1], bh0[3]);

                mma_bf16(acc[2], ah, bh1[0], bh1[2]);
                mma_bf16(acc[2], ah, bl1[0], bl1[2]);
                mma_bf16(acc[2], al, bh1[0], bh1[2]);

                mma_bf16(acc[3], ah, bh1[1], bh1[3]);
                mma_bf16(acc[3], ah, bl1[1], bl1[3]);
                mma_bf16(acc[3], al, bh1[1], bh1[3]);
            }
        }

        #pragma unroll
        for (int half = 0; half < 2; half++) {
            const int em = m0 + half * 8;
            float hv[2];
            #pragma unroll
            for (int j = 0; j < 2; j++) {
                const int q = half * 2 + j;
                float fg = fast_sigmoid(acc[0][q] + xp[0][q]);
                float ig = fast_sigmoid(acc[1][q] + xp[1][q]);
                float gg = fast_tanh(acc[2][q] + xp[2][q]);
                float og = fast_sigmoid(acc[3][q] + xp[3][q]);
                float c2 = fg * creg[q] + ig * gg;
                creg[q] = c2;
                hv[j] = og * fast_tanh(c2);
            }
            *(float2*)&g_h[(size_t)em * NH + en0] = make_float2(hv[0], hv[1]);

            __nv_bfloat162 hh = __floats2bfloat162_rn(hv[0], hv[1]);
            float l0 = hv[0] - __bfloat162float(__low2bfloat16(hh));
            float l1 = hv[1] - __bfloat162float(__high2bfloat16(hh));
            const size_t byte = (size_t)kc_h * 16384u
                              + swz128((uint32_t)em * 128u + col_h * 2u);
            *(__nv_bfloat162*)((char*)hout_hi + byte) = hh;
            *(__nv_bfloat162*)((char*)hout_lo + byte) = __floats2bfloat162_rn(l0, l1);
        }

        if (t < SEQ - 1) {
            __threadfence();
            __syncthreads();
            if (tid == 0) {
                atomicAdd(&g_sync, 1u);
                const unsigned target = (unsigned)(RBLOCKS * (t + 1));
                while (*((volatile unsigned*)&g_sync) < target) { }
            }
            __syncthreads();
        }
    }

    #pragma unroll
    for (int half = 0; half < 2; half++) {
        const int em = m0 + half * 8;
        *(float2*)&g_c[(size_t)em * NH + en0] = make_float2(creg[half * 2], creg[half * 2 + 1]);
    }
}

// ---------------- proj v2: bulk-copy fed 128m x 128n bf16x3 GEMM ----------------
// grid (32, 256): x = gate*8 + nsub (128-wide n within gate), y = m-tile (128 rows).
// 256 threads, 8 warps: warp = (wm 0..3 m-quarter 32m, wn 0..1 n-half 64n).
// Stage (64KB): [0,16K) A hi (128 m x 128B swz), [16K,32K) A lo,
// [32K,48K) B hi (128 n x 128B swz), [48K,64K) B lo. 2 stages.
__global__ __launch_bounds__(256) void proj_gemm(Ptr4 Bias)
{
    extern __shared__ __align__(128) unsigned char dynsm[];
    const uint32_t smem_u32 = (uint32_t)__cvta_generic_to_shared(dynsm);

    const int tid  = threadIdx.x;
    const int warp = tid >> 5;
    const int lane = tid & 31;
    const int gate = blockIdx.x >> 3;
    const int nsub = blockIdx.x & 7;
    const int mbase = blockIdx.y * 128;

    if (tid == 0) {
        mbar_init(smem_u32 + 0, 1);
        mbar_init(smem_u32 + 8, 1);
        fence_async_shared();
    }
    __syncthreads();

    const char* srcA0 = (const char*)g_xr_hi + (size_t)mbase * 128;
    const char* srcA1 = (const char*)g_xr_lo + (size_t)mbase * 128;
    const char* srcB0 = (const char*)g_Wxr_hi + (size_t)gate * 1048576u + (size_t)nsub * 16384u;
    const char* srcB1 = (const char*)g_Wxr_lo + (size_t)gate * 1048576u + (size_t)nsub * 16384u;

    // prologue: chunk 0 -> stage 0
    if (tid == 0) {
        mbar_expect_tx(smem_u32 + 0, 65536u);
        bulk_copy(smem_u32 + 1024,          srcA0, 16384u, smem_u32 + 0);
        bulk_copy(smem_u32 + 1024 + 16384,  srcA1, 16384u, smem_u32 + 0);
        bulk_copy(smem_u32 + 1024 + 32768,  srcB0, 16384u, smem_u32 + 0);
        bulk_copy(smem_u32 + 1024 + 49152,  srcB1, 16384u, smem_u32 + 0);
    }

    const int wm = warp >> 1;     // m-quarter (32m)
    const int wn = warp & 1;      // n-half (64n)
    const int frow  = lane & 15;
    const int fhalf = (lane >> 4) << 4;

    float acc[2][8][4];
    #pragma unroll
    for (int mt = 0; mt < 2; mt++) {
        #pragma unroll
        for (int j = 0; j < 8; j++) {
            #pragma unroll
            for (int q = 0; q < 4; q++) { acc[mt][j][q] = 0.f; }
        }
    }

    for (int c = 0; c < PKC; c++) {
        const int st = c & 1;
        mbar_wait(smem_u32 + st * 8, (uint32_t)((c >> 1) & 1));
        __syncthreads();

        const int cn = c + 1;
        if (cn < PKC && tid == 0) {
            const int stn = cn & 1;
            fence_async_shared();
            mbar_expect_tx(smem_u32 + stn * 8, 65536u);
            const uint32_t dst = smem_u32 + 1024 + (uint32_t)(stn * PSTG);
            bulk_copy(dst,          srcA0 + (size_t)cn * 4194304u, 16384u, smem_u32 + stn * 8);
            bulk_copy(dst + 16384,  srcA1 + (size_t)cn * 4194304u, 16384u, smem_u32 + stn * 8);
            bulk_copy(dst + 32768,  srcB0 + (size_t)cn * 131072u, 16384u, smem_u32 + stn * 8);
            bulk_copy(dst + 49152,  srcB1 + (size_t)cn * 131072u, 16384u, smem_u32 + stn * 8);
        }

        const uint32_t su = smem_u32 + 1024 + (uint32_t)(st * PSTG);
        #pragma unroll
        for (int ks = 0; ks < 4; ks++) {
            uint32_t ah[2][4]; uint32_t al[2][4];
            uint32_t bh[4][4]; uint32_t bl[4][4];
            #pragma unroll
            for (int mt = 0; mt < 2; mt++) {
                const uint32_t oa = (uint32_t)((wm * 32 + mt * 16 + frow) * 128
                                               + ks * 32 + fhalf);
                ldsm4(ah[mt], su + swz128(oa));
                ldsm4(al[mt], su + 16384u + swz128(oa));
            }
            #pragma unroll
            for (int bt = 0; bt < 4; bt++) {
                const uint32_t ob = (uint32_t)((wn * 64 + bt * 16 + frow) * 128
                                               + ks * 32 + fhalf);
                ldsm4(bh[bt], su + 32768u + swz128(ob));
                ldsm4(bl[bt], su + 49152u + swz128(ob));
            }
            #pragma unroll
            for (int mt = 0; mt < 2; mt++) {
                #pragma unroll
                for (int bt = 0; bt < 4; bt++) {
                    mma_bf16(acc[mt][bt * 2 + 0], ah[mt], bh[bt][0], bh[bt][2]);
                    mma_bf16(acc[mt][bt * 2 + 0], ah[mt], bl[bt][0], bl[bt][2]);
                    mma_bf16(acc[mt][bt * 2 + 0], al[mt], bh[bt][0], bh[bt][2]);

                    mma_bf16(acc[mt][bt * 2 + 1], ah[mt], bh[bt][1], bh[bt][3]);
                    mma_bf16(acc[mt][bt * 2 + 1], ah[mt], bl[bt][1], bl[bt][3]);
                    mma_bf16(acc[mt][bt * 2 + 1], al[mt], bh[bt][1], bh[bt][3]);
                }
            }
        }
    }

    __syncthreads();
    // stage 128x128 fp32 in smem (64KB overlay on pipeline buffers)
    float* stage = (float*)(dynsm + 1024);
    {
        const int row  = lane >> 2;
        const int colp = (lane & 3) * 2;
        #pragma unroll
        for (int mt = 0; mt < 2; mt++) {
            #pragma unroll
            for (int j = 0; j < 8; j++) {
                const int r0 = wm * 32 + mt * 16 + row;
                const int cc = wn * 64 + j * 8 + colp;
                stage[r0 * 128 + cc]       = acc[mt][j][0];
                stage[r0 * 128 + cc + 1]   = acc[mt][j][1];
                stage[(r0 + 8) * 128 + cc]     = acc[mt][j][2];
                stage[(r0 + 8) * 128 + cc + 1] = acc[mt][j][3];
            }
        }
    }
    __syncthreads();

    // permuted + biased write to g_xproj
    const float* __restrict__ bias = Bias.p[gate];
    #pragma unroll
    for (int i = 0; i < 16; i++) {
        const int e   = i * 256 + tid;       // 4096 float4 groups
        const int row = e >> 5;
        const int c4  = (e & 31) * 4;
        const int m   = mbase + row;
        const int bb  = m >> 8;              // m = b*SEQ + s, SEQ = 256
        const int ss  = m & 255;
        const int col = nsub * 128 + c4;
        float4 v = *(float4*)(stage + row * 128 + c4);
        v.x += bias[col + 0];
        v.y += bias[col + 1];
        v.z += bias[col + 2];
        v.w += bias[col + 3];
        *(float4*)&g_xproj[(((size_t)gate * SEQ + ss) * BATCH + bb) * NH + col] = v;
    }
}

// ---------------- fp32 output GEMM (small) ----------------
__global__ __launch_bounds__(256) void out_gemm(const float* __restrict__ Wy,
                                                const float* __restrict__ by,
                                                float* __restrict__ out)
{
    __shared__ float As[TK][SROW];
    __shared__ float Bs[TK][SROW];
    const int tid = threadIdx.x;
    const int tx = tid & 15;
    const int ty = tid >> 4;
    const int mbase = blockIdx.y * TM;
    const int nbase = blockIdx.x * TN;
    const int lm = tid >> 2;
    const int lk = (tid & 3) << 2;

    float acc[4][4];
    #pragma unroll
    for (int i = 0; i < 4; i++) {
        #pragma unroll
        for (int j = 0; j < 4; j++) { acc[i][j] = 0.f; }
    }

    for (int kt = 0; kt < NH; kt += TK) {
        float4 av = *(const float4*)&g_h[(size_t)(mbase + lm) * NH + kt + lk];
        float4 bv = *(const float4*)&Wy [(size_t)(nbase + lm) * NH + kt + lk];
        __syncthreads();
        As[lk + 0][lm] = av.x; As[lk + 1][lm] = av.y;
        As[lk + 2][lm] = av.z; As[lk + 3][lm] = av.w;
        Bs[lk + 0][lm] = bv.x; Bs[lk + 1][lm] = bv.y;
        Bs[lk + 2][lm] = bv.z; Bs[lk + 3][lm] = bv.w;
        __syncthreads();
        #pragma unroll
        for (int k = 0; k < TK; k++) {
            float ar[4]; float br[4];
            #pragma unroll
            for (int i = 0; i < 4; i++) { ar[i] = As[k][(ty << 2) + i]; }
            #pragma unroll
            for (int j = 0; j < 4; j++) { br[j] = Bs[k][(tx << 2) + j]; }
            #pragma unroll
            for (int i = 0; i < 4; i++) {
                #pragma unroll
                for (int j = 0; j < 4; j++) { acc[i][j] = fmaf(ar[i], br[j], acc[i][j]); }
            }
        }
    }

    #pragma unroll
    for (int i = 0; i < 4; i++) {
        int m = mbase + (ty << 2) + i;
        int n0 = nbase + (tx << 2);
        #pragma unroll
        for (int j = 0; j < 4; j++) {
            out[(size_t)m * NOUT + n0 + j] = acc[i][j] + by[n0 + j];
        }
    }
}

__global__ __launch_bounds__(256) void copy_hc(float* __restrict__ out)
{
    const int idx = blockIdx.x * 256 + threadIdx.x;  // grid 512
    out[(size_t)BATCH * NOUT + idx]                      = g_h[idx];
    out[(size_t)BATCH * NOUT + (size_t)BATCH * NH + idx] = g_c[idx];
}

// ---------------------------------------------------------------------------
extern "C" void kernel_launch(void* const* d_in, const int* in_sizes, int n_in,
                              void* d_out, int out_size)
{
    const float* x_seq = (const float*)d_in[0];
    Ptr4 Wx; Ptr4 Bx; Ptr4 Wh;
    Wx.p[0] = (const float*)d_in[1];  Bx.p[0] = (const float*)d_in[2];  Wh.p[0] = (const float*)d_in[3];
    Wx.p[1] = (const float*)d_in[4];  Bx.p[1] = (const float*)d_in[5];  Wh.p[1] = (const float*)d_in[6];
    Wx.p[2] = (const float*)d_in[7];  Bx.p[2] = (const float*)d_in[8];  Wh.p[2] = (const float*)d_in[9];
    Wx.p[3] = (const float*)d_in[10]; Bx.p[3] = (const float*)d_in[11]; Wh.p[3] = (const float*)d_in[12];
    const float* Why_w = (const float*)d_in[13];
    const float* Why_b = (const float*)d_in[14];
    float* out = (float*)d_out;

    cudaFuncSetAttribute(rec_persistent, cudaFuncAttributeMaxDynamicSharedMemorySize, REC_SMEM);
    cudaFuncSetAttribute(proj_gemm, cudaFuncAttributeMaxDynamicSharedMemorySize, PROJ_SMEM);

    fused_setup<<<65536, 256>>>(x_seq, Wh, Wx);

    proj_gemm<<<dim3(32, 256), 256, PROJ_SMEM>>>(Bx);

    rec_persistent<<<RBLOCKS, 256, REC_SMEM>>>();

    out_gemm<<<dim3(NOUT / TN, BATCH / TM), 256>>>(Why_w, Why_b, out);
    copy_hc<<<512, 256>>>(out);
}